// round 1
// baseline (speedup 1.0000x reference)
#include <cuda_runtime.h>

// ============================================================================
// AxialAttention: x[8,128,128,256], two axial self-attentions (8 heads, e=32)
// out = proj(attn_H(x)) + proj(attn_W(x)).   All fp32, f32x2 FFMA fast path.
// ============================================================================

#define NTOK 131072          // 8*128*128 tokens
#define CDIM 256

// Scratch (device globals: allocation-guard safe)
__device__ float g_Q[NTOK * CDIM];
__device__ float g_K[NTOK * CDIM];
__device__ float g_V[NTOK * CDIM];
__device__ float g_O[NTOK * CDIM];

typedef unsigned long long ull;

__device__ __forceinline__ ull splat2(float x) {
    ull r; asm("mov.b64 %0, {%1, %1};" : "=l"(r) : "f"(x)); return r;
}
__device__ __forceinline__ ull ffma2(ull a, ull b, ull c) {
    ull d; asm("fma.rn.f32x2 %0, %1, %2, %3;" : "=l"(d) : "l"(a), "l"(b), "l"(c)); return d;
}
__device__ __forceinline__ float2 unpack2(ull v) {
    float2 f; asm("mov.b64 {%0, %1}, %2;" : "=f"(f.x), "=f"(f.y) : "l"(v)); return f;
}

// ============================================================================
// GEMM: C[M,256] = alpha * A[M,256] @ B[256x256 slice of ldb-stride matrix]
//        (+ bias[col]) (+= existing C if ACCUM).  M = NTOK.  BM=BN=128, BK=16.
// 256 threads; per thread 8(m) x 8(n) outputs as 4 f32x2 m-pairs x 8 n.
// ============================================================================
#define ASTR 132   // smem stride for A^T tile (16B aligned, conflict-reduced)

template<bool ACCUM, bool HASBIAS>
__global__ void __launch_bounds__(256, 2)
gemm_k256(const float* __restrict__ A, const float* __restrict__ B,
          float* __restrict__ C, int ldb, float alpha,
          const float* __restrict__ bias)
{
    __shared__ __align__(16) float Ast[16 * ASTR];  // Ast[k][m]
    __shared__ __align__(16) float Bs[16 * 128];    // Bs[k][n]

    const int t  = threadIdx.x;
    const int tr = t >> 4;          // 0..15 -> rows tr*8..+7
    const int tc = t & 15;          // 0..15 -> cols tc*8..+7
    const int rowBase = blockIdx.y * 128;
    const int colBase = blockIdx.x * 128;

    const float* Ab = A + (size_t)rowBase * 256;
    const float* Bb = B + colBase;

    ull acc[4][8];
#pragma unroll
    for (int i = 0; i < 4; i++)
#pragma unroll
        for (int j = 0; j < 8; j++) acc[i][j] = 0ull;

    float4 ra[2], rb[2];

    // prologue: load tile kb=0
#pragma unroll
    for (int i = 0; i < 2; i++) {
        int f = i * 256 + t;
        int r = f >> 2, cg = f & 3;
        ra[i] = *(const float4*)(Ab + r * 256 + cg * 4);
        int rB = f >> 5, cB = (f & 31) << 2;
        rb[i] = *(const float4*)(Bb + rB * ldb + cB);
    }
#pragma unroll
    for (int i = 0; i < 2; i++) {
        int f = i * 256 + t;
        int r = f >> 2, cg = f & 3;
        Ast[(cg * 4 + 0) * ASTR + r] = ra[i].x;
        Ast[(cg * 4 + 1) * ASTR + r] = ra[i].y;
        Ast[(cg * 4 + 2) * ASTR + r] = ra[i].z;
        Ast[(cg * 4 + 3) * ASTR + r] = ra[i].w;
        int rB = f >> 5, cB = (f & 31) << 2;
        *(float4*)(Bs + rB * 128 + cB) = rb[i];
    }
    __syncthreads();

    for (int kb = 0; kb < 16; kb++) {
        if (kb < 15) {   // prefetch next tile into registers (overlaps compute)
#pragma unroll
            for (int i = 0; i < 2; i++) {
                int f = i * 256 + t;
                int r = f >> 2, cg = f & 3;
                ra[i] = *(const float4*)(Ab + r * 256 + (kb + 1) * 16 + cg * 4);
                int rB = f >> 5, cB = (f & 31) << 2;
                rb[i] = *(const float4*)(Bb + ((kb + 1) * 16 + rB) * ldb + cB);
            }
        }
#pragma unroll
        for (int k = 0; k < 16; k++) {
            ulonglong2 a01 = *(const ulonglong2*)(Ast + k * ASTR + tr * 8);
            ulonglong2 a23 = *(const ulonglong2*)(Ast + k * ASTR + tr * 8 + 4);
            float4 b0 = *(const float4*)(Bs + k * 128 + tc * 8);
            float4 b1 = *(const float4*)(Bs + k * 128 + tc * 8 + 4);
            ull ap[4] = { a01.x, a01.y, a23.x, a23.y };
            ull bp[8] = { splat2(b0.x), splat2(b0.y), splat2(b0.z), splat2(b0.w),
                          splat2(b1.x), splat2(b1.y), splat2(b1.z), splat2(b1.w) };
#pragma unroll
            for (int i = 0; i < 4; i++)
#pragma unroll
                for (int j = 0; j < 8; j++)
                    acc[i][j] = ffma2(ap[i], bp[j], acc[i][j]);
        }
        __syncthreads();
        if (kb < 15) {
#pragma unroll
            for (int i = 0; i < 2; i++) {
                int f = i * 256 + t;
                int r = f >> 2, cg = f & 3;
                Ast[(cg * 4 + 0) * ASTR + r] = ra[i].x;
                Ast[(cg * 4 + 1) * ASTR + r] = ra[i].y;
                Ast[(cg * 4 + 2) * ASTR + r] = ra[i].z;
                Ast[(cg * 4 + 3) * ASTR + r] = ra[i].w;
                int rB = f >> 5, cB = (f & 31) << 2;
                *(float4*)(Bs + rB * 128 + cB) = rb[i];
            }
            __syncthreads();
        }
    }

    // epilogue
    const int cbase = colBase + tc * 8;
    float bb[8];
#pragma unroll
    for (int j = 0; j < 8; j++) bb[j] = 0.f;
    if (HASBIAS) {
        float4 b0 = *(const float4*)(bias + cbase);
        float4 b1 = *(const float4*)(bias + cbase + 4);
        bb[0] = b0.x; bb[1] = b0.y; bb[2] = b0.z; bb[3] = b0.w;
        bb[4] = b1.x; bb[5] = b1.y; bb[6] = b1.z; bb[7] = b1.w;
    }
#pragma unroll
    for (int i2 = 0; i2 < 4; i2++) {
        float r0[8], r1[8];
#pragma unroll
        for (int j = 0; j < 8; j++) {
            float2 v = unpack2(acc[i2][j]);
            r0[j] = v.x * alpha + bb[j];
            r1[j] = v.y * alpha + bb[j];
        }
        int mA = rowBase + tr * 8 + i2 * 2;
        float* p0 = C + (size_t)mA * 256 + cbase;
        float* p1 = p0 + 256;
        if (ACCUM) {
            float4 o00 = *(float4*)p0, o01 = *(float4*)(p0 + 4);
            float4 o10 = *(float4*)p1, o11 = *(float4*)(p1 + 4);
            r0[0] += o00.x; r0[1] += o00.y; r0[2] += o00.z; r0[3] += o00.w;
            r0[4] += o01.x; r0[5] += o01.y; r0[6] += o01.z; r0[7] += o01.w;
            r1[0] += o10.x; r1[1] += o10.y; r1[2] += o10.z; r1[3] += o10.w;
            r1[4] += o11.x; r1[5] += o11.y; r1[6] += o11.z; r1[7] += o11.w;
        }
        float4 s;
        s.x = r0[0]; s.y = r0[1]; s.z = r0[2]; s.w = r0[3]; *(float4*)p0 = s;
        s.x = r0[4]; s.y = r0[5]; s.z = r0[6]; s.w = r0[7]; *(float4*)(p0 + 4) = s;
        s.x = r1[0]; s.y = r1[1]; s.z = r1[2]; s.w = r1[3]; *(float4*)p1 = s;
        s.x = r1[4]; s.y = r1[5]; s.z = r1[6]; s.w = r1[7]; *(float4*)(p1 + 4) = s;
    }
}

// ============================================================================
// Attention: one block per (sequence, head). seqlen=128, e=32.
// S = (Q*e^-0.5) K^T (scale pre-folded into Q), softmax rows, O = P V.
// smem: Vs[128][32] | Qt[32][128] | Kt[32][128] ; Ps[128][132] overlaps Qt/Kt.
// ============================================================================
#define PSTR 132
#define ATTN_SMEM_FLOATS (4096 + 128 * PSTR + 128)
#define ATTN_SMEM_BYTES (ATTN_SMEM_FLOATS * 4)

__global__ void __launch_bounds__(256, 2)
attn_kernel(const float* __restrict__ Q, const float* __restrict__ K,
            const float* __restrict__ V, float* __restrict__ O, int axis)
{
    extern __shared__ __align__(16) float sm[];
    float* Vs = sm;                       // [128][32]
    float* Qt = sm + 4096;                // [32][128]  (c-major)
    float* Kt = sm + 8192;                // [32][128]
    float* Ps = sm + 4096;                // [128][PSTR], overlaps Qt/Kt (dead after S)
    float* rowSum = sm + 4096 + 128 * PSTR;

    const int s = blockIdx.x;             // sequence id (0..1023)
    const int head = blockIdx.y;          // 0..7
    int tokBase, tokStride;
    if (axis == 0) { int b = s >> 7, w = s & 127; tokBase = b * 16384 + w; tokStride = 128; }
    else           { tokBase = s * 128; tokStride = 1; }
    const int chanOff = head * 32;
    const int t = threadIdx.x;

    // ---- load Q,K (transposed to c-major) and V tiles ----
    {
        int p = t >> 1, c0 = (t & 1) * 16;
        const size_t gbase = (size_t)(tokBase + p * tokStride) * 256 + chanOff + c0;
#pragma unroll
        for (int q = 0; q < 4; q++) {
            float4 qv = *(const float4*)(Q + gbase + q * 4);
            float4 kv = *(const float4*)(K + gbase + q * 4);
            float4 vv = *(const float4*)(V + gbase + q * 4);
            int c = c0 + q * 4;
            Qt[(c + 0) * 128 + p] = qv.x; Qt[(c + 1) * 128 + p] = qv.y;
            Qt[(c + 2) * 128 + p] = qv.z; Qt[(c + 3) * 128 + p] = qv.w;
            Kt[(c + 0) * 128 + p] = kv.x; Kt[(c + 1) * 128 + p] = kv.y;
            Kt[(c + 2) * 128 + p] = kv.z; Kt[(c + 3) * 128 + p] = kv.w;
            *(float4*)(Vs + p * 32 + c) = vv;
        }
    }
    __syncthreads();

    // ---- S = Q K^T  (thread (tr,tc): rows tr*8..+7, cols tc*8..+7) ----
    const int tr = t >> 4, tc = t & 15;
    ull acc[8][4];
#pragma unroll
    for (int i = 0; i < 8; i++)
#pragma unroll
        for (int j = 0; j < 4; j++) acc[i][j] = 0ull;

#pragma unroll 4
    for (int c = 0; c < 32; c++) {
        float4 qa = *(const float4*)(Qt + c * 128 + tr * 8);
        float4 qb = *(const float4*)(Qt + c * 128 + tr * 8 + 4);
        ulonglong2 k01 = *(const ulonglong2*)(Kt + c * 128 + tc * 8);
        ulonglong2 k23 = *(const ulonglong2*)(Kt + c * 128 + tc * 8 + 4);
        ull kp[4] = { k01.x, k01.y, k23.x, k23.y };
        ull qs[8] = { splat2(qa.x), splat2(qa.y), splat2(qa.z), splat2(qa.w),
                      splat2(qb.x), splat2(qb.y), splat2(qb.z), splat2(qb.w) };
#pragma unroll
        for (int i = 0; i < 8; i++)
#pragma unroll
            for (int j = 0; j < 4; j++)
                acc[i][j] = ffma2(qs[i], kp[j], acc[i][j]);
    }
    __syncthreads();   // Qt/Kt fully consumed; Ps may now overwrite them

    // ---- row softmax (16 threads per row share via shfl, width 16) ----
#pragma unroll
    for (int i = 0; i < 8; i++) {
        float e[8];
        {
            float2 v0 = unpack2(acc[i][0]), v1 = unpack2(acc[i][1]);
            float2 v2 = unpack2(acc[i][2]), v3 = unpack2(acc[i][3]);
            e[0] = v0.x; e[1] = v0.y; e[2] = v1.x; e[3] = v1.y;
            e[4] = v2.x; e[5] = v2.y; e[6] = v3.x; e[7] = v3.y;
        }
        float mx = e[0];
#pragma unroll
        for (int j = 1; j < 8; j++) mx = fmaxf(mx, e[j]);
#pragma unroll
        for (int d = 8; d >= 1; d >>= 1)
            mx = fmaxf(mx, __shfl_xor_sync(0xffffffffu, mx, d, 16));
        float sum = 0.f;
#pragma unroll
        for (int j = 0; j < 8; j++) { e[j] = __expf(e[j] - mx); sum += e[j]; }
#pragma unroll
        for (int d = 8; d >= 1; d >>= 1)
            sum += __shfl_xor_sync(0xffffffffu, sum, d, 16);
        int r = tr * 8 + i;
        float4 w;
        w.x = e[0]; w.y = e[1]; w.z = e[2]; w.w = e[3];
        *(float4*)(Ps + r * PSTR + tc * 8) = w;
        w.x = e[4]; w.y = e[5]; w.z = e[6]; w.w = e[7];
        *(float4*)(Ps + r * PSTR + tc * 8 + 4) = w;
        if (tc == 0) rowSum[r] = sum;
    }
    __syncthreads();

    // ---- O = P V  (thread (rp,cp): rows rp*4..+3, cols cp*4..+3) ----
    const int rp = t >> 3, cp = t & 7;
    ull av[4][2];
#pragma unroll
    for (int i = 0; i < 4; i++) { av[i][0] = 0ull; av[i][1] = 0ull; }

#pragma unroll 2
    for (int k4 = 0; k4 < 32; k4++) {
        float pr[4][4];
#pragma unroll
        for (int i = 0; i < 4; i++) {
            float4 p4 = *(const float4*)(Ps + (rp * 4 + i) * PSTR + k4 * 4);
            pr[i][0] = p4.x; pr[i][1] = p4.y; pr[i][2] = p4.z; pr[i][3] = p4.w;
        }
#pragma unroll
        for (int kk = 0; kk < 4; kk++) {
            ulonglong2 vv = *(const ulonglong2*)(Vs + (k4 * 4 + kk) * 32 + cp * 4);
#pragma unroll
            for (int i = 0; i < 4; i++) {
                ull pp = splat2(pr[i][kk]);
                av[i][0] = ffma2(pp, vv.x, av[i][0]);
                av[i][1] = ffma2(pp, vv.y, av[i][1]);
            }
        }
    }

    // ---- normalize + write ----
#pragma unroll
    for (int i = 0; i < 4; i++) {
        int r = rp * 4 + i;
        float inv = 1.0f / rowSum[r];
        float2 e0 = unpack2(av[i][0]);
        float2 e1 = unpack2(av[i][1]);
        float4 o;
        o.x = e0.x * inv; o.y = e0.y * inv; o.z = e1.x * inv; o.w = e1.y * inv;
        size_t g = (size_t)(tokBase + r * tokStride) * 256 + chanOff + cp * 4;
        *(float4*)(O + g) = o;
    }
}

// ============================================================================
// Host launcher
// ============================================================================
extern "C" void kernel_launch(void* const* d_in, const int* in_sizes, int n_in,
                              void* d_out, int out_size)
{
    (void)in_sizes; (void)n_in; (void)out_size;
    const float* x     = (const float*)d_in[0];
    const float* Wq0   = (const float*)d_in[1];
    const float* Wkv0  = (const float*)d_in[2];
    const float* Wout0 = (const float*)d_in[3];
    const float* bout0 = (const float*)d_in[4];
    const float* Wq1   = (const float*)d_in[5];
    const float* Wkv1  = (const float*)d_in[6];
    const float* Wout1 = (const float*)d_in[7];
    const float* bout1 = (const float*)d_in[8];
    float* out = (float*)d_out;

    float *Qb, *Kb, *Vb, *Ob;
    cudaGetSymbolAddress((void**)&Qb, g_Q);
    cudaGetSymbolAddress((void**)&Kb, g_K);
    cudaGetSymbolAddress((void**)&Vb, g_V);
    cudaGetSymbolAddress((void**)&Ob, g_O);

    cudaFuncSetAttribute(attn_kernel,
                         cudaFuncAttributeMaxDynamicSharedMemorySize,
                         ATTN_SMEM_BYTES);

    const dim3 gg(2, NTOK / 128);       // (col tiles, row tiles)
    const dim3 ga(1024, 8);             // (sequences, heads)
    const float scale = 0.17677669529663687f;   // 32^-0.5 folded into Q

    // ---- axis 0 (attention along H) ----
    gemm_k256<false, false><<<gg, 256>>>(x, Wq0,        Qb, 256, scale, nullptr);
    gemm_k256<false, false><<<gg, 256>>>(x, Wkv0,       Kb, 512, 1.f,   nullptr);
    gemm_k256<false, false><<<gg, 256>>>(x, Wkv0 + 256, Vb, 512, 1.f,   nullptr);
    attn_kernel<<<ga, 256, ATTN_SMEM_BYTES>>>(Qb, Kb, Vb, Ob, 0);
    gemm_k256<false, true><<<gg, 256>>>(Ob, Wout0, out, 256, 1.f, bout0);

    // ---- axis 1 (attention along W), accumulate into out ----
    gemm_k256<false, false><<<gg, 256>>>(x, Wq1,        Qb, 256, scale, nullptr);
    gemm_k256<false, false><<<gg, 256>>>(x, Wkv1,       Kb, 512, 1.f,   nullptr);
    gemm_k256<false, false><<<gg, 256>>>(x, Wkv1 + 256, Vb, 512, 1.f,   nullptr);
    attn_kernel<<<ga, 256, ATTN_SMEM_BYTES>>>(Qb, Kb, Vb, Ob, 1);
    gemm_k256<true, true><<<gg, 256>>>(Ob, Wout1, out, 256, 1.f, bout1);
}

// round 3
// speedup vs baseline: 1.6000x; 1.6000x over previous
#include <cuda_runtime.h>
#include <cuda_bf16.h>

// ============================================================================
// AxialAttention — bf16x3 split GEMMs on mma.sync (HMMA) + fp32 SIMT attention
// (baseline sm_100 ISA only: mma.sync / ldmatrix / cp.async — no tcgen05)
// ============================================================================

#define NTOK 131072          // 8*128*128 tokens
#define CDIM 256

// ---- scratch (device globals: allocation-guard safe) ----
__device__ __nv_bfloat16 g_xh[NTOK * CDIM];
__device__ __nv_bfloat16 g_xl[NTOK * CDIM];
__device__ float         g_Q [NTOK * CDIM];
__device__ float         g_K [NTOK * CDIM];
__device__ float         g_V [NTOK * CDIM];
__device__ __nv_bfloat16 g_Oh[NTOK * CDIM];
__device__ __nv_bfloat16 g_Ol[NTOK * CDIM];
__device__ __nv_bfloat16 g_Wb[8 * 2 * 65536];   // 8 mats: [hi 256n x 256k][lo ...]

typedef unsigned long long ull;
typedef unsigned int       u32;
typedef unsigned short     u16;

__device__ __forceinline__ u32 smem_u32(const void* p) {
    u32 a;
    asm("{ .reg .u64 t; cvta.to.shared.u64 t, %1; cvt.u32.u64 %0, t; }" : "=r"(a) : "l"(p));
    return a;
}
__device__ __forceinline__ void cpasync16(u32 dst, const void* src) {
    asm volatile("cp.async.cg.shared.global [%0], [%1], 16;" :: "r"(dst), "l"(src));
}
__device__ __forceinline__ void cp_commit() {
    asm volatile("cp.async.commit_group;" ::: "memory");
}
template<int N> __device__ __forceinline__ void cp_wait() {
    asm volatile("cp.async.wait_group %0;" :: "n"(N) : "memory");
}
__device__ __forceinline__ void ldsm4(u32* r, u32 addr) {
    asm volatile("ldmatrix.sync.aligned.m8n8.x4.shared.b16 {%0,%1,%2,%3}, [%4];"
                 : "=r"(r[0]), "=r"(r[1]), "=r"(r[2]), "=r"(r[3]) : "r"(addr));
}
__device__ __forceinline__ void mma16816(float* c, const u32* a, u32 b0, u32 b1) {
    asm volatile(
        "mma.sync.aligned.m16n8k16.row.col.f32.bf16.bf16.f32 "
        "{%0,%1,%2,%3}, {%4,%5,%6,%7}, {%8,%9}, {%0,%1,%2,%3};"
        : "+f"(c[0]), "+f"(c[1]), "+f"(c[2]), "+f"(c[3])
        : "r"(a[0]), "r"(a[1]), "r"(a[2]), "r"(a[3]), "r"(b0), "r"(b1));
}

// f32x2 helpers (attention core)
__device__ __forceinline__ ull splat2(float x) {
    ull r; asm("mov.b64 %0, {%1, %1};" : "=l"(r) : "f"(x)); return r;
}
__device__ __forceinline__ ull ffma2(ull a, ull b, ull c) {
    ull d; asm("fma.rn.f32x2 %0, %1, %2, %3;" : "=l"(d) : "l"(a), "l"(b), "l"(c)); return d;
}
__device__ __forceinline__ float2 unpack2(ull v) {
    float2 f; asm("mov.b64 {%0, %1}, %2;" : "=f"(f.x), "=f"(f.y) : "l"(v)); return f;
}

// bf16 hi/lo split
__device__ __forceinline__ void split1(float v, u16& h, u16& l) {
    __nv_bfloat16 hb = __float2bfloat16(v);
    float hf = __bfloat162float(hb);
    __nv_bfloat16 lb = __float2bfloat16(v - hf);
    h = __bfloat16_as_ushort(hb);
    l = __bfloat16_as_ushort(lb);
}

// ============================================================================
// Prep kernels
// ============================================================================
__global__ void prep_weights(const float* __restrict__ Wq0, const float* __restrict__ Wkv0,
                             const float* __restrict__ Wout0,
                             const float* __restrict__ Wq1, const float* __restrict__ Wkv1,
                             const float* __restrict__ Wout1,
                             __nv_bfloat16* __restrict__ Wb)
{
    const int m = blockIdx.x;      // 0..7 : [q0,k0,v0,o0,q1,k1,v1,o1]
    const int slab = blockIdx.y;   // 0..7
    const float* W;
    int ld = 256, coff = 0;
    float scale = 1.0f;
    switch (m & 3) {
        case 0: W = (m < 4) ? Wq0 : Wq1; scale = 0.17677669529663687f; break;  // 32^-0.5
        case 1: W = (m < 4) ? Wkv0 : Wkv1; ld = 512; break;
        case 2: W = (m < 4) ? Wkv0 : Wkv1; ld = 512; coff = 256; break;
        default: W = (m < 4) ? Wout0 : Wout1; break;
    }
    u16* dh = (u16*)(Wb + (size_t)m * 131072);
    u16* dl = dh + 65536;
    for (int e = threadIdx.x; e < 8192; e += 256) {
        int n = slab * 32 + (e >> 8);
        int k = e & 255;
        float v = W[k * ld + coff + n] * scale;   // B[n][k] = W[k][n]
        u16 h, l; split1(v, h, l);
        dh[n * 256 + k] = h;
        dl[n * 256 + k] = l;
    }
}

__global__ void split_x_kernel(const float* __restrict__ x,
                               __nv_bfloat16* __restrict__ xh,
                               __nv_bfloat16* __restrict__ xl)
{
    size_t i = ((size_t)blockIdx.x * 256 + threadIdx.x) * 4;
    float4 v = *(const float4*)(x + i);
    ushort4 h, l;
    split1(v.x, h.x, l.x); split1(v.y, h.y, l.y);
    split1(v.z, h.z, l.z); split1(v.w, h.w, l.w);
    *(ushort4*)((u16*)xh + i) = h;
    *(ushort4*)((u16*)xl + i) = l;
}

// ============================================================================
// HMMA GEMM: C[M,256] = (Ah+Al)[M,256k] @ (Bh+Bl)^T  (B stored [n][k])
// Block tile 128m x 128n x 32k, double-buffered cp.async, bf16x3 passes.
// 8 warps = 2(m) x 4(n); warp tile 64m x 32n = 4 m-frags x 4 n-frags.
// smem per stage: Ah|Al|Bh|Bl, each 128 rows x 32 k, padded row = 80 B.
// ============================================================================
#define GS_ROWB   80                       // padded row bytes (40 bf16)
#define GS_PART   10240                    // 128 * 80
#define GS_STAGE  40960                    // 4 parts
#define GS_SMEM   81920                    // 2 stages

template<bool ACCUM, bool HASBIAS>
__global__ void __launch_bounds__(256)
gemm_mma(const __nv_bfloat16* __restrict__ Ah, const __nv_bfloat16* __restrict__ Al,
         const __nv_bfloat16* __restrict__ Bm, float* __restrict__ C,
         const float* __restrict__ bias)
{
    extern __shared__ __align__(128) char smem[];
    const u32 sb = smem_u32(smem);
    const int t = threadIdx.x;
    const int l = t & 31;
    const int wid = t >> 5;
    const int wm = wid >> 2;               // 0..1
    const int wn = wid & 3;                // 0..3
    const int rowBase = blockIdx.y << 7;
    const int colBase = blockIdx.x << 7;

    const __nv_bfloat16* Bh = Bm;
    const __nv_bfloat16* Bl = Bm + 65536;

    float acc[4][4][4];
#pragma unroll
    for (int i = 0; i < 4; i++)
#pragma unroll
        for (int j = 0; j < 4; j++)
#pragma unroll
            for (int q = 0; q < 4; q++) acc[i][j][q] = 0.f;

    // per-thread cp.async mapping: idx = t + i*256 -> row = idx>>2, chunk = idx&3
    const int lr = t >> 2, lc = t & 3;

    // per-thread ldmatrix row offset within a 16-row fragment
    const u32 lmOff = (u32)((l & 15) * GS_ROWB + (l >> 4) * 16);

    // ---- prefetch k-chunk kc into stage s ----
    auto prefetch = [&](int s, int kc) {
        const u32 stb = sb + s * GS_STAGE;
        const int kcol = kc * 32;
#pragma unroll
        for (int i = 0; i < 2; i++) {
            const int r = lr + i * 64;
            const u32 doff = (u32)(r * GS_ROWB + lc * 16);
            const size_t gA = (size_t)(rowBase + r) * 256 + kcol + lc * 8;
            const size_t gB = (size_t)(colBase + r) * 256 + kcol + lc * 8;
            cpasync16(stb + doff,                 Ah + gA);
            cpasync16(stb + GS_PART + doff,       Al + gA);
            cpasync16(stb + 2 * GS_PART + doff,   Bh + gB);
            cpasync16(stb + 3 * GS_PART + doff,   Bl + gB);
        }
        cp_commit();
    };

    prefetch(0, 0);

    for (int kc = 0; kc < 8; kc++) {
        const int s = kc & 1;
        if (kc < 7) prefetch(s ^ 1, kc + 1);
        if (kc < 7) cp_wait<1>(); else cp_wait<0>();
        __syncthreads();

        const u32 stb = sb + s * GS_STAGE;
#pragma unroll
        for (int ks = 0; ks < 2; ks++) {
            u32 ah[4][4], al[4][4];
#pragma unroll
            for (int mf = 0; mf < 4; mf++) {
                const u32 a = stb + (u32)((wm * 64 + mf * 16) * GS_ROWB + ks * 32) + lmOff;
                ldsm4(ah[mf], a);
                ldsm4(al[mf], a + GS_PART);
            }
            u32 bh[2][4], bl[2][4];
#pragma unroll
            for (int g = 0; g < 2; g++) {
                const u32 b = stb + 2 * GS_PART
                            + (u32)((wn * 32 + g * 16) * GS_ROWB + ks * 32) + lmOff;
                ldsm4(bh[g], b);
                ldsm4(bl[g], b + GS_PART);
            }
#pragma unroll
            for (int mf = 0; mf < 4; mf++)
#pragma unroll
                for (int nf = 0; nf < 4; nf++) {
                    const int g = nf >> 1, j = nf & 1;
                    mma16816(acc[mf][nf], ah[mf], bh[g][j], bh[g][j + 2]);
                    mma16816(acc[mf][nf], al[mf], bh[g][j], bh[g][j + 2]);
                    mma16816(acc[mf][nf], ah[mf], bl[g][j], bl[g][j + 2]);
                }
        }
        __syncthreads();
    }

    // ---- epilogue ----
#pragma unroll
    for (int mf = 0; mf < 4; mf++) {
        const int m0 = rowBase + wm * 64 + mf * 16 + (l >> 2);
#pragma unroll
        for (int nf = 0; nf < 4; nf++) {
            const int col = colBase + wn * 32 + nf * 8 + 2 * (l & 3);
            float2 v0 = make_float2(acc[mf][nf][0], acc[mf][nf][1]);
            float2 v1 = make_float2(acc[mf][nf][2], acc[mf][nf][3]);
            if (HASBIAS) {
                float2 b = *(const float2*)(bias + col);
                v0.x += b.x; v0.y += b.y; v1.x += b.x; v1.y += b.y;
            }
            float* p0 = C + (size_t)m0 * 256 + col;
            float* p1 = p0 + 8 * 256;
            if (ACCUM) {
                float2 c0 = *(float2*)p0, c1 = *(float2*)p1;
                v0.x += c0.x; v0.y += c0.y; v1.x += c1.x; v1.y += c1.y;
            }
            *(float2*)p0 = v0;
            *(float2*)p1 = v1;
        }
    }
}

// ============================================================================
// Attention: one block per (sequence, head). seqlen=128, e=32. fp32 SIMT.
// Outputs written as bf16 hi/lo split for the HMMA out-projection.
// ============================================================================
#define PSTR 132
#define ATTN_SMEM_FLOATS (4096 + 128 * PSTR + 128)
#define ATTN_SMEM_BYTES (ATTN_SMEM_FLOATS * 4)

__global__ void __launch_bounds__(256, 2)
attn_kernel(const float* __restrict__ Q, const float* __restrict__ K,
            const float* __restrict__ V,
            __nv_bfloat16* __restrict__ Oh, __nv_bfloat16* __restrict__ Ol, int axis)
{
    extern __shared__ __align__(16) float smf[];
    float* Vs = smf;                       // [128][32]
    float* Qt = smf + 4096;                // [32][128]  (c-major)
    float* Kt = smf + 8192;                // [32][128]
    float* Ps = smf + 4096;                // [128][PSTR], overlaps Qt/Kt
    float* rowSum = smf + 4096 + 128 * PSTR;

    const int s = blockIdx.x;
    const int head = blockIdx.y;
    int tokBase, tokStride;
    if (axis == 0) { int b = s >> 7, w = s & 127; tokBase = b * 16384 + w; tokStride = 128; }
    else           { tokBase = s * 128; tokStride = 1; }
    const int chanOff = head * 32;
    const int t = threadIdx.x;

    {
        int p = t >> 1, c0 = (t & 1) * 16;
        const size_t gbase = (size_t)(tokBase + p * tokStride) * 256 + chanOff + c0;
#pragma unroll
        for (int q = 0; q < 4; q++) {
            float4 qv = *(const float4*)(Q + gbase + q * 4);
            float4 kv = *(const float4*)(K + gbase + q * 4);
            float4 vv = *(const float4*)(V + gbase + q * 4);
            int c = c0 + q * 4;
            Qt[(c + 0) * 128 + p] = qv.x; Qt[(c + 1) * 128 + p] = qv.y;
            Qt[(c + 2) * 128 + p] = qv.z; Qt[(c + 3) * 128 + p] = qv.w;
            Kt[(c + 0) * 128 + p] = kv.x; Kt[(c + 1) * 128 + p] = kv.y;
            Kt[(c + 2) * 128 + p] = kv.z; Kt[(c + 3) * 128 + p] = kv.w;
            *(float4*)(Vs + p * 32 + c) = vv;
        }
    }
    __syncthreads();

    const int tr = t >> 4, tc = t & 15;
    ull acc[8][4];
#pragma unroll
    for (int i = 0; i < 8; i++)
#pragma unroll
        for (int j = 0; j < 4; j++) acc[i][j] = 0ull;

#pragma unroll 4
    for (int c = 0; c < 32; c++) {
        float4 qa = *(const float4*)(Qt + c * 128 + tr * 8);
        float4 qb = *(const float4*)(Qt + c * 128 + tr * 8 + 4);
        ulonglong2 k01 = *(const ulonglong2*)(Kt + c * 128 + tc * 8);
        ulonglong2 k23 = *(const ulonglong2*)(Kt + c * 128 + tc * 8 + 4);
        ull kp[4] = { k01.x, k01.y, k23.x, k23.y };
        ull qs[8] = { splat2(qa.x), splat2(qa.y), splat2(qa.z), splat2(qa.w),
                      splat2(qb.x), splat2(qb.y), splat2(qb.z), splat2(qb.w) };
#pragma unroll
        for (int i = 0; i < 8; i++)
#pragma unroll
            for (int j = 0; j < 4; j++)
                acc[i][j] = ffma2(qs[i], kp[j], acc[i][j]);
    }
    __syncthreads();

#pragma unroll
    for (int i = 0; i < 8; i++) {
        float e[8];
        {
            float2 v0 = unpack2(acc[i][0]), v1 = unpack2(acc[i][1]);
            float2 v2 = unpack2(acc[i][2]), v3 = unpack2(acc[i][3]);
            e[0] = v0.x; e[1] = v0.y; e[2] = v1.x; e[3] = v1.y;
            e[4] = v2.x; e[5] = v2.y; e[6] = v3.x; e[7] = v3.y;
        }
        float mx = e[0];
#pragma unroll
        for (int j = 1; j < 8; j++) mx = fmaxf(mx, e[j]);
#pragma unroll
        for (int d = 8; d >= 1; d >>= 1)
            mx = fmaxf(mx, __shfl_xor_sync(0xffffffffu, mx, d, 16));
        float sum = 0.f;
#pragma unroll
        for (int j = 0; j < 8; j++) { e[j] = __expf(e[j] - mx); sum += e[j]; }
#pragma unroll
        for (int d = 8; d >= 1; d >>= 1)
            sum += __shfl_xor_sync(0xffffffffu, sum, d, 16);
        int r = tr * 8 + i;
        float4 w;
        w.x = e[0]; w.y = e[1]; w.z = e[2]; w.w = e[3];
        *(float4*)(Ps + r * PSTR + tc * 8) = w;
        w.x = e[4]; w.y = e[5]; w.z = e[6]; w.w = e[7];
        *(float4*)(Ps + r * PSTR + tc * 8 + 4) = w;
        if (tc == 0) rowSum[r] = sum;
    }
    __syncthreads();

    const int rp = t >> 3, cp = t & 7;
    ull av[4][2];
#pragma unroll
    for (int i = 0; i < 4; i++) { av[i][0] = 0ull; av[i][1] = 0ull; }

#pragma unroll 2
    for (int k4 = 0; k4 < 32; k4++) {
        float pr[4][4];
#pragma unroll
        for (int i = 0; i < 4; i++) {
            float4 p4 = *(const float4*)(Ps + (rp * 4 + i) * PSTR + k4 * 4);
            pr[i][0] = p4.x; pr[i][1] = p4.y; pr[i][2] = p4.z; pr[i][3] = p4.w;
        }
#pragma unroll
        for (int kk = 0; kk < 4; kk++) {
            ulonglong2 vv = *(const ulonglong2*)(Vs + (k4 * 4 + kk) * 32 + cp * 4);
#pragma unroll
            for (int i = 0; i < 4; i++) {
                ull pp = splat2(pr[i][kk]);
                av[i][0] = ffma2(pp, vv.x, av[i][0]);
                av[i][1] = ffma2(pp, vv.y, av[i][1]);
            }
        }
    }

#pragma unroll
    for (int i = 0; i < 4; i++) {
        int r = rp * 4 + i;
        float inv = 1.0f / rowSum[r];
        float2 e0 = unpack2(av[i][0]);
        float2 e1 = unpack2(av[i][1]);
        float ov[4] = { e0.x * inv, e0.y * inv, e1.x * inv, e1.y * inv };
        ushort4 h4, l4;
        split1(ov[0], h4.x, l4.x); split1(ov[1], h4.y, l4.y);
        split1(ov[2], h4.z, l4.z); split1(ov[3], h4.w, l4.w);
        size_t g = (size_t)(tokBase + r * tokStride) * 256 + chanOff + cp * 4;
        *(ushort4*)((u16*)Oh + g) = h4;
        *(ushort4*)((u16*)Ol + g) = l4;
    }
}

// ============================================================================
// Host launcher
// ============================================================================
extern "C" void kernel_launch(void* const* d_in, const int* in_sizes, int n_in,
                              void* d_out, int out_size)
{
    (void)in_sizes; (void)n_in; (void)out_size;
    const float* x     = (const float*)d_in[0];
    const float* Wq0   = (const float*)d_in[1];
    const float* Wkv0  = (const float*)d_in[2];
    const float* Wout0 = (const float*)d_in[3];
    const float* bout0 = (const float*)d_in[4];
    const float* Wq1   = (const float*)d_in[5];
    const float* Wkv1  = (const float*)d_in[6];
    const float* Wout1 = (const float*)d_in[7];
    const float* bout1 = (const float*)d_in[8];
    float* out = (float*)d_out;

    __nv_bfloat16 *xh, *xl, *Ohb, *Olb, *Wb;
    float *Qb, *Kb, *Vb;
    cudaGetSymbolAddress((void**)&xh, g_xh);
    cudaGetSymbolAddress((void**)&xl, g_xl);
    cudaGetSymbolAddress((void**)&Qb, g_Q);
    cudaGetSymbolAddress((void**)&Kb, g_K);
    cudaGetSymbolAddress((void**)&Vb, g_V);
    cudaGetSymbolAddress((void**)&Ohb, g_Oh);
    cudaGetSymbolAddress((void**)&Olb, g_Ol);
    cudaGetSymbolAddress((void**)&Wb, g_Wb);

    cudaFuncSetAttribute(gemm_mma<false, false>,
                         cudaFuncAttributeMaxDynamicSharedMemorySize, GS_SMEM);
    cudaFuncSetAttribute(gemm_mma<false, true>,
                         cudaFuncAttributeMaxDynamicSharedMemorySize, GS_SMEM);
    cudaFuncSetAttribute(gemm_mma<true, true>,
                         cudaFuncAttributeMaxDynamicSharedMemorySize, GS_SMEM);
    cudaFuncSetAttribute(attn_kernel,
                         cudaFuncAttributeMaxDynamicSharedMemorySize, ATTN_SMEM_BYTES);

    const dim3 gg(2, 1024);    // (n tiles, m tiles)
    const dim3 ga(1024, 8);    // (sequences, heads)

    prep_weights<<<dim3(8, 8), 256>>>(Wq0, Wkv0, Wout0, Wq1, Wkv1, Wout1, Wb);
    split_x_kernel<<<32768, 256>>>(x, xh, xl);

    // ---- axis 0 ----
    gemm_mma<false, false><<<gg, 256, GS_SMEM>>>(xh, xl, Wb + 0u * 131072, Qb, nullptr);
    gemm_mma<false, false><<<gg, 256, GS_SMEM>>>(xh, xl, Wb + 1u * 131072, Kb, nullptr);
    gemm_mma<false, false><<<gg, 256, GS_SMEM>>>(xh, xl, Wb + 2u * 131072, Vb, nullptr);
    attn_kernel<<<ga, 256, ATTN_SMEM_BYTES>>>(Qb, Kb, Vb, Ohb, Olb, 0);
    gemm_mma<false, true><<<gg, 256, GS_SMEM>>>(Ohb, Olb, Wb + 3u * 131072, out, bout0);

    // ---- axis 1 ----
    gemm_mma<false, false><<<gg, 256, GS_SMEM>>>(xh, xl, Wb + 4u * 131072, Qb, nullptr);
    gemm_mma<false, false><<<gg, 256, GS_SMEM>>>(xh, xl, Wb + 5u * 131072, Kb, nullptr);
    gemm_mma<false, false><<<gg, 256, GS_SMEM>>>(xh, xl, Wb + 6u * 131072, Vb, nullptr);
    attn_kernel<<<ga, 256, ATTN_SMEM_BYTES>>>(Qb, Kb, Vb, Ohb, Olb, 1);
    gemm_mma<true, true><<<gg, 256, GS_SMEM>>>(Ohb, Olb, Wb + 7u * 131072, out, bout1);
}

// round 4
// speedup vs baseline: 1.9417x; 1.2136x over previous
#include <cuda_runtime.h>
#include <cuda_bf16.h>

// ============================================================================
// AxialAttention — bf16x3 HMMA GEMMs + bf16x3 HMMA attention core
// (baseline sm_100 ISA: mma.sync / ldmatrix / cp.async — no tcgen05)
// ============================================================================

#define NTOK 131072          // 8*128*128 tokens
#define CDIM 256

// ---- scratch (device globals: allocation-guard safe) ----
__device__ __nv_bfloat16 g_xh[NTOK * CDIM];
__device__ __nv_bfloat16 g_xl[NTOK * CDIM];
__device__ __nv_bfloat16 g_Qh[NTOK * CDIM];
__device__ __nv_bfloat16 g_Ql[NTOK * CDIM];
__device__ __nv_bfloat16 g_Kh[NTOK * CDIM];
__device__ __nv_bfloat16 g_Kl[NTOK * CDIM];
__device__ __nv_bfloat16 g_Vh[NTOK * CDIM];
__device__ __nv_bfloat16 g_Vl[NTOK * CDIM];
__device__ __nv_bfloat16 g_Oh[NTOK * CDIM];
__device__ __nv_bfloat16 g_Ol[NTOK * CDIM];
__device__ __nv_bfloat16 g_Wb[8 * 2 * 65536];   // 8 mats: [hi 256n x 256k][lo ...]

typedef unsigned long long ull;
typedef unsigned int       u32;
typedef unsigned short     u16;

__device__ __forceinline__ u32 smem_u32(const void* p) {
    u32 a;
    asm("{ .reg .u64 t; cvta.to.shared.u64 t, %1; cvt.u32.u64 %0, t; }" : "=r"(a) : "l"(p));
    return a;
}
__device__ __forceinline__ void cpasync16(u32 dst, const void* src) {
    asm volatile("cp.async.cg.shared.global [%0], [%1], 16;" :: "r"(dst), "l"(src));
}
__device__ __forceinline__ void cp_commit() {
    asm volatile("cp.async.commit_group;" ::: "memory");
}
template<int N> __device__ __forceinline__ void cp_wait() {
    asm volatile("cp.async.wait_group %0;" :: "n"(N) : "memory");
}
__device__ __forceinline__ void ldsm4(u32* r, u32 addr) {
    asm volatile("ldmatrix.sync.aligned.m8n8.x4.shared.b16 {%0,%1,%2,%3}, [%4];"
                 : "=r"(r[0]), "=r"(r[1]), "=r"(r[2]), "=r"(r[3]) : "r"(addr));
}
__device__ __forceinline__ void ldsm4t(u32* r, u32 addr) {
    asm volatile("ldmatrix.sync.aligned.m8n8.x4.trans.shared.b16 {%0,%1,%2,%3}, [%4];"
                 : "=r"(r[0]), "=r"(r[1]), "=r"(r[2]), "=r"(r[3]) : "r"(addr));
}
__device__ __forceinline__ void mma16816(float* c, const u32* a, u32 b0, u32 b1) {
    asm volatile(
        "mma.sync.aligned.m16n8k16.row.col.f32.bf16.bf16.f32 "
        "{%0,%1,%2,%3}, {%4,%5,%6,%7}, {%8,%9}, {%0,%1,%2,%3};"
        : "+f"(c[0]), "+f"(c[1]), "+f"(c[2]), "+f"(c[3])
        : "r"(a[0]), "r"(a[1]), "r"(a[2]), "r"(a[3]), "r"(b0), "r"(b1));
}
__device__ __forceinline__ u32 cvt_bf16x2(float hi, float lo) {
    u32 r;
    asm("cvt.rn.satfinite.bf16x2.f32 %0, %1, %2;" : "=r"(r) : "f"(hi), "f"(lo));
    return r;
}

// bf16 hi/lo split
__device__ __forceinline__ void split1(float v, u16& h, u16& l) {
    __nv_bfloat16 hb = __float2bfloat16(v);
    float hf = __bfloat162float(hb);
    __nv_bfloat16 lb = __float2bfloat16(v - hf);
    h = __bfloat16_as_ushort(hb);
    l = __bfloat16_as_ushort(lb);
}
// split a pair (e0 -> low half, e1 -> high half), producing hi-word and lo-word
__device__ __forceinline__ void split_pair(float e0, float e1, u32& hw, u32& lw) {
    __nv_bfloat16 h0 = __float2bfloat16(e0);
    __nv_bfloat16 h1 = __float2bfloat16(e1);
    hw = ((u32)__bfloat16_as_ushort(h1) << 16) | (u32)__bfloat16_as_ushort(h0);
    lw = cvt_bf16x2(e1 - __bfloat162float(h1), e0 - __bfloat162float(h0));
}

// ============================================================================
// Prep kernels
// ============================================================================
__global__ void prep_weights(const float* __restrict__ Wq0, const float* __restrict__ Wkv0,
                             const float* __restrict__ Wout0,
                             const float* __restrict__ Wq1, const float* __restrict__ Wkv1,
                             const float* __restrict__ Wout1,
                             __nv_bfloat16* __restrict__ Wb)
{
    const int m = blockIdx.x;      // 0..7 : [q0,k0,v0,o0,q1,k1,v1,o1]
    const int slab = blockIdx.y;   // 0..7
    const float* W;
    int ld = 256, coff = 0;
    float scale = 1.0f;
    switch (m & 3) {
        case 0: W = (m < 4) ? Wq0 : Wq1; scale = 0.17677669529663687f; break;  // 32^-0.5
        case 1: W = (m < 4) ? Wkv0 : Wkv1; ld = 512; break;
        case 2: W = (m < 4) ? Wkv0 : Wkv1; ld = 512; coff = 256; break;
        default: W = (m < 4) ? Wout0 : Wout1; break;
    }
    u16* dh = (u16*)(Wb + (size_t)m * 131072);
    u16* dl = dh + 65536;
    for (int e = threadIdx.x; e < 8192; e += 256) {
        int n = slab * 32 + (e >> 8);
        int k = e & 255;
        float v = W[k * ld + coff + n] * scale;   // B[n][k] = W[k][n]
        u16 h, l; split1(v, h, l);
        dh[n * 256 + k] = h;
        dl[n * 256 + k] = l;
    }
}

__global__ void split_x_kernel(const float* __restrict__ x,
                               __nv_bfloat16* __restrict__ xh,
                               __nv_bfloat16* __restrict__ xl)
{
    size_t i = ((size_t)blockIdx.x * 256 + threadIdx.x) * 4;
    float4 v = *(const float4*)(x + i);
    ushort4 h, l;
    split1(v.x, h.x, l.x); split1(v.y, h.y, l.y);
    split1(v.z, h.z, l.z); split1(v.w, h.w, l.w);
    *(ushort4*)((u16*)xh + i) = h;
    *(ushort4*)((u16*)xl + i) = l;
}

// ============================================================================
// HMMA GEMM: C = (Ah+Al)[M,256k] @ (Bh+Bl)^T  (B stored [n][k])
// OMODE: 0 = f32 out; 1 = f32 + bias; 2 = f32 + bias + accum; 3 = bf16 hi/lo out
// ============================================================================
#define GS_ROWB   80
#define GS_PART   10240
#define GS_STAGE  40960
#define GS_SMEM   81920

template<int OMODE>
__global__ void __launch_bounds__(256)
gemm_mma(const __nv_bfloat16* __restrict__ Ah, const __nv_bfloat16* __restrict__ Al,
         const __nv_bfloat16* __restrict__ Bm, float* __restrict__ C,
         __nv_bfloat16* __restrict__ Ch, __nv_bfloat16* __restrict__ Cl,
         const float* __restrict__ bias)
{
    extern __shared__ __align__(128) char smem[];
    const u32 sb = smem_u32(smem);
    const int t = threadIdx.x;
    const int l = t & 31;
    const int wid = t >> 5;
    const int wm = wid >> 2;
    const int wn = wid & 3;
    const int rowBase = blockIdx.y << 7;
    const int colBase = blockIdx.x << 7;

    const __nv_bfloat16* Bh = Bm;
    const __nv_bfloat16* Bl = Bm + 65536;

    float acc[4][4][4];
#pragma unroll
    for (int i = 0; i < 4; i++)
#pragma unroll
        for (int j = 0; j < 4; j++)
#pragma unroll
            for (int q = 0; q < 4; q++) acc[i][j][q] = 0.f;

    const int lr = t >> 2, lc = t & 3;
    const u32 lmOff = (u32)((l & 15) * GS_ROWB + (l >> 4) * 16);

    auto prefetch = [&](int s, int kc) {
        const u32 stb = sb + s * GS_STAGE;
        const int kcol = kc * 32;
#pragma unroll
        for (int i = 0; i < 2; i++) {
            const int r = lr + i * 64;
            const u32 doff = (u32)(r * GS_ROWB + lc * 16);
            const size_t gA = (size_t)(rowBase + r) * 256 + kcol + lc * 8;
            const size_t gB = (size_t)(colBase + r) * 256 + kcol + lc * 8;
            cpasync16(stb + doff,                 Ah + gA);
            cpasync16(stb + GS_PART + doff,       Al + gA);
            cpasync16(stb + 2 * GS_PART + doff,   Bh + gB);
            cpasync16(stb + 3 * GS_PART + doff,   Bl + gB);
        }
        cp_commit();
    };

    prefetch(0, 0);

    for (int kc = 0; kc < 8; kc++) {
        const int s = kc & 1;
        if (kc < 7) prefetch(s ^ 1, kc + 1);
        if (kc < 7) cp_wait<1>(); else cp_wait<0>();
        __syncthreads();

        const u32 stb = sb + s * GS_STAGE;
#pragma unroll
        for (int ks = 0; ks < 2; ks++) {
            u32 ah[4][4], al[4][4];
#pragma unroll
            for (int mf = 0; mf < 4; mf++) {
                const u32 a = stb + (u32)((wm * 64 + mf * 16) * GS_ROWB + ks * 32) + lmOff;
                ldsm4(ah[mf], a);
                ldsm4(al[mf], a + GS_PART);
            }
            u32 bh[2][4], bl[2][4];
#pragma unroll
            for (int g = 0; g < 2; g++) {
                const u32 b = stb + 2 * GS_PART
                            + (u32)((wn * 32 + g * 16) * GS_ROWB + ks * 32) + lmOff;
                ldsm4(bh[g], b);
                ldsm4(bl[g], b + GS_PART);
            }
#pragma unroll
            for (int mf = 0; mf < 4; mf++)
#pragma unroll
                for (int nf = 0; nf < 4; nf++) {
                    const int g = nf >> 1, j = nf & 1;
                    mma16816(acc[mf][nf], ah[mf], bh[g][j], bh[g][j + 2]);
                    mma16816(acc[mf][nf], al[mf], bh[g][j], bh[g][j + 2]);
                    mma16816(acc[mf][nf], ah[mf], bl[g][j], bl[g][j + 2]);
                }
        }
        __syncthreads();
    }

    // ---- epilogue ----
#pragma unroll
    for (int mf = 0; mf < 4; mf++) {
        const int m0 = rowBase + wm * 64 + mf * 16 + (l >> 2);
#pragma unroll
        for (int nf = 0; nf < 4; nf++) {
            const int col = colBase + wn * 32 + nf * 8 + 2 * (l & 3);
            float2 v0 = make_float2(acc[mf][nf][0], acc[mf][nf][1]);
            float2 v1 = make_float2(acc[mf][nf][2], acc[mf][nf][3]);
            if (OMODE == 3) {
                u32 h0, l0, h1, l1;
                split_pair(v0.x, v0.y, h0, l0);
                split_pair(v1.x, v1.y, h1, l1);
                const size_t i0 = (size_t)m0 * 256 + col;
                const size_t i1 = i0 + 8 * 256;
                *(u32*)((u16*)Ch + i0) = h0;
                *(u32*)((u16*)Cl + i0) = l0;
                *(u32*)((u16*)Ch + i1) = h1;
                *(u32*)((u16*)Cl + i1) = l1;
            } else {
                if (OMODE >= 1) {
                    float2 b = *(const float2*)(bias + col);
                    v0.x += b.x; v0.y += b.y; v1.x += b.x; v1.y += b.y;
                }
                float* p0 = C + (size_t)m0 * 256 + col;
                float* p1 = p0 + 8 * 256;
                if (OMODE == 2) {
                    float2 c0 = *(float2*)p0, c1 = *(float2*)p1;
                    v0.x += c0.x; v0.y += c0.y; v1.x += c1.x; v1.y += c1.y;
                }
                *(float2*)p0 = v0;
                *(float2*)p1 = v1;
            }
        }
    }
}

// ============================================================================
// HMMA attention: one block per (sequence, head). seqlen=128, e=32.
// 8 warps; warp w owns query rows w*16..w*16+15 (full row of S -> quad-only
// softmax reductions). bf16x3 on both S = QK^T and O = PV.
// smem: Qh|Ql|Kh|Kl|Vh|Vl tiles, each 128 rows x 32 chan, 80B row stride.
// ============================================================================
#define AT_ROWB 80
#define AT_TILE 10240
#define AT_SMEM (6 * AT_TILE)   // 61440

__global__ void __launch_bounds__(256, 2)
attn_mma(const __nv_bfloat16* __restrict__ Qh, const __nv_bfloat16* __restrict__ Ql,
         const __nv_bfloat16* __restrict__ Kh, const __nv_bfloat16* __restrict__ Kl,
         const __nv_bfloat16* __restrict__ Vh, const __nv_bfloat16* __restrict__ Vl,
         __nv_bfloat16* __restrict__ Oh, __nv_bfloat16* __restrict__ Ol, int axis)
{
    extern __shared__ __align__(128) char smem[];
    const u32 sb = smem_u32(smem);
    const int t = threadIdx.x;
    const int l = t & 31;
    const int w = t >> 5;

    const int s = blockIdx.x;
    const int head = blockIdx.y;
    int tokBase, tokStride;
    if (axis == 0) { int b = s >> 7, ww = s & 127; tokBase = b * 16384 + ww; tokStride = 128; }
    else           { tokBase = s * 128; tokStride = 1; }
    const int chanOff = head * 32;

    // ---- load 6 tiles (cp.async, one shot) ----
    {
        const __nv_bfloat16* srcs[6] = { Qh, Ql, Kh, Kl, Vh, Vl };
#pragma unroll
        for (int tile = 0; tile < 6; tile++) {
            const u16* src = (const u16*)srcs[tile];
#pragma unroll
            for (int i = 0; i < 2; i++) {
                const int c = t + i * 256;
                const int row = c >> 2, cg = c & 3;
                const size_t g = (size_t)(tokBase + row * tokStride) * 256 + chanOff + cg * 8;
                cpasync16(sb + tile * AT_TILE + row * AT_ROWB + cg * 16, src + g);
            }
        }
        cp_commit();
        cp_wait<0>();
        __syncthreads();
    }

    const u32 lmOff = (u32)((l & 15) * AT_ROWB + (l >> 4) * 16);

    // ---- S = Q K^T (bf16x3), warp strip rows w*16..+15, full 128 cols ----
    float sv[16][4];
#pragma unroll
    for (int nf = 0; nf < 16; nf++)
#pragma unroll
        for (int q = 0; q < 4; q++) sv[nf][q] = 0.f;

#pragma unroll
    for (int kc = 0; kc < 2; kc++) {
        u32 aqh[4], aql[4];
        const u32 qa = sb + (u32)(w * 16 * AT_ROWB + kc * 32) + lmOff;
        ldsm4(aqh, qa);
        ldsm4(aql, qa + AT_TILE);
#pragma unroll
        for (int g = 0; g < 8; g++) {
            u32 kh4[4], kl4[4];
            const u32 ka = sb + 2 * AT_TILE + (u32)(g * 16 * AT_ROWB + kc * 32) + lmOff;
            ldsm4(kh4, ka);
            ldsm4(kl4, ka + AT_TILE);
#pragma unroll
            for (int j = 0; j < 2; j++) {
                const int nf = g * 2 + j;
                mma16816(sv[nf], aqh, kh4[j], kh4[j + 2]);
                mma16816(sv[nf], aql, kh4[j], kh4[j + 2]);
                mma16816(sv[nf], aqh, kl4[j], kl4[j + 2]);
            }
        }
    }

    // ---- softmax (rows fully in-warp: quad shuffles only) ----
    float mx0 = -1e30f, mx1 = -1e30f;
#pragma unroll
    for (int nf = 0; nf < 16; nf++) {
        mx0 = fmaxf(mx0, fmaxf(sv[nf][0], sv[nf][1]));
        mx1 = fmaxf(mx1, fmaxf(sv[nf][2], sv[nf][3]));
    }
    mx0 = fmaxf(mx0, __shfl_xor_sync(0xffffffffu, mx0, 1));
    mx0 = fmaxf(mx0, __shfl_xor_sync(0xffffffffu, mx0, 2));
    mx1 = fmaxf(mx1, __shfl_xor_sync(0xffffffffu, mx1, 1));
    mx1 = fmaxf(mx1, __shfl_xor_sync(0xffffffffu, mx1, 2));

    float sum0 = 0.f, sum1 = 0.f;
#pragma unroll
    for (int nf = 0; nf < 16; nf++) {
        sv[nf][0] = __expf(sv[nf][0] - mx0);
        sv[nf][1] = __expf(sv[nf][1] - mx0);
        sv[nf][2] = __expf(sv[nf][2] - mx1);
        sv[nf][3] = __expf(sv[nf][3] - mx1);
        sum0 += sv[nf][0] + sv[nf][1];
        sum1 += sv[nf][2] + sv[nf][3];
    }
    sum0 += __shfl_xor_sync(0xffffffffu, sum0, 1);
    sum0 += __shfl_xor_sync(0xffffffffu, sum0, 2);
    sum1 += __shfl_xor_sync(0xffffffffu, sum1, 1);
    sum1 += __shfl_xor_sync(0xffffffffu, sum1, 2);
    const float inv0 = 1.0f / sum0;
    const float inv1 = 1.0f / sum1;

    // ---- O = P V (bf16x3); P frags built in-register from S C-frags ----
    float ao[4][4];
#pragma unroll
    for (int nf = 0; nf < 4; nf++)
#pragma unroll
        for (int q = 0; q < 4; q++) ao[nf][q] = 0.f;

#pragma unroll
    for (int jc = 0; jc < 8; jc++) {
        u32 ph[4], pl[4];
        split_pair(sv[2 * jc][0],     sv[2 * jc][1],     ph[0], pl[0]);
        split_pair(sv[2 * jc][2],     sv[2 * jc][3],     ph[1], pl[1]);
        split_pair(sv[2 * jc + 1][0], sv[2 * jc + 1][1], ph[2], pl[2]);
        split_pair(sv[2 * jc + 1][2], sv[2 * jc + 1][3], ph[3], pl[3]);
#pragma unroll
        for (int eg = 0; eg < 2; eg++) {
            u32 vh4[4], vl4[4];
            const u32 va = sb + 4 * AT_TILE + (u32)(jc * 16 * AT_ROWB + eg * 32) + lmOff;
            ldsm4t(vh4, va);
            ldsm4t(vl4, va + AT_TILE);
#pragma unroll
            for (int j = 0; j < 2; j++) {
                const int nf = eg * 2 + j;
                mma16816(ao[nf], ph, vh4[j * 2], vh4[j * 2 + 1]);
                mma16816(ao[nf], pl, vh4[j * 2], vh4[j * 2 + 1]);
                mma16816(ao[nf], ph, vl4[j * 2], vl4[j * 2 + 1]);
            }
        }
    }

    // ---- normalize + write bf16 hi/lo ----
    const int row0 = w * 16 + (l >> 2);
    const int row1 = row0 + 8;
    const size_t tok0 = (size_t)(tokBase + row0 * tokStride) * 256;
    const size_t tok1 = (size_t)(tokBase + row1 * tokStride) * 256;
#pragma unroll
    for (int nf = 0; nf < 4; nf++) {
        const int col = chanOff + nf * 8 + 2 * (l & 3);
        u32 h0, l0, h1, l1;
        split_pair(ao[nf][0] * inv0, ao[nf][1] * inv0, h0, l0);
        split_pair(ao[nf][2] * inv1, ao[nf][3] * inv1, h1, l1);
        *(u32*)((u16*)Oh + tok0 + col) = h0;
        *(u32*)((u16*)Ol + tok0 + col) = l0;
        *(u32*)((u16*)Oh + tok1 + col) = h1;
        *(u32*)((u16*)Ol + tok1 + col) = l1;
    }
}

// ============================================================================
// Host launcher
// ============================================================================
extern "C" void kernel_launch(void* const* d_in, const int* in_sizes, int n_in,
                              void* d_out, int out_size)
{
    (void)in_sizes; (void)n_in; (void)out_size;
    const float* x     = (const float*)d_in[0];
    const float* Wq0   = (const float*)d_in[1];
    const float* Wkv0  = (const float*)d_in[2];
    const float* Wout0 = (const float*)d_in[3];
    const float* bout0 = (const float*)d_in[4];
    const float* Wq1   = (const float*)d_in[5];
    const float* Wkv1  = (const float*)d_in[6];
    const float* Wout1 = (const float*)d_in[7];
    const float* bout1 = (const float*)d_in[8];
    float* out = (float*)d_out;

    __nv_bfloat16 *xh, *xl, *Qhb, *Qlb, *Khb, *Klb, *Vhb, *Vlb, *Ohb, *Olb, *Wb;
    cudaGetSymbolAddress((void**)&xh,  g_xh);
    cudaGetSymbolAddress((void**)&xl,  g_xl);
    cudaGetSymbolAddress((void**)&Qhb, g_Qh);
    cudaGetSymbolAddress((void**)&Qlb, g_Ql);
    cudaGetSymbolAddress((void**)&Khb, g_Kh);
    cudaGetSymbolAddress((void**)&Klb, g_Kl);
    cudaGetSymbolAddress((void**)&Vhb, g_Vh);
    cudaGetSymbolAddress((void**)&Vlb, g_Vl);
    cudaGetSymbolAddress((void**)&Ohb, g_Oh);
    cudaGetSymbolAddress((void**)&Olb, g_Ol);
    cudaGetSymbolAddress((void**)&Wb,  g_Wb);

    cudaFuncSetAttribute(gemm_mma<1>,
                         cudaFuncAttributeMaxDynamicSharedMemorySize, GS_SMEM);
    cudaFuncSetAttribute(gemm_mma<2>,
                         cudaFuncAttributeMaxDynamicSharedMemorySize, GS_SMEM);
    cudaFuncSetAttribute(gemm_mma<3>,
                         cudaFuncAttributeMaxDynamicSharedMemorySize, GS_SMEM);
    cudaFuncSetAttribute(attn_mma,
                         cudaFuncAttributeMaxDynamicSharedMemorySize, AT_SMEM);

    const dim3 gg(2, 1024);    // (n tiles, m tiles)
    const dim3 ga(1024, 8);    // (sequences, heads)

    prep_weights<<<dim3(8, 8), 256>>>(Wq0, Wkv0, Wout0, Wq1, Wkv1, Wout1, Wb);
    split_x_kernel<<<32768, 256>>>(x, xh, xl);

    // ---- axis 0 ----
    gemm_mma<3><<<gg, 256, GS_SMEM>>>(xh, xl, Wb + 0u * 131072, nullptr, Qhb, Qlb, nullptr);
    gemm_mma<3><<<gg, 256, GS_SMEM>>>(xh, xl, Wb + 1u * 131072, nullptr, Khb, Klb, nullptr);
    gemm_mma<3><<<gg, 256, GS_SMEM>>>(xh, xl, Wb + 2u * 131072, nullptr, Vhb, Vlb, nullptr);
    attn_mma<<<ga, 256, AT_SMEM>>>(Qhb, Qlb, Khb, Klb, Vhb, Vlb, Ohb, Olb, 0);
    gemm_mma<1><<<gg, 256, GS_SMEM>>>(Ohb, Olb, Wb + 3u * 131072, out, nullptr, nullptr, bout0);

    // ---- axis 1 ----
    gemm_mma<3><<<gg, 256, GS_SMEM>>>(xh, xl, Wb + 4u * 131072, nullptr, Qhb, Qlb, nullptr);
    gemm_mma<3><<<gg, 256, GS_SMEM>>>(xh, xl, Wb + 5u * 131072, nullptr, Khb, Klb, nullptr);
    gemm_mma<3><<<gg, 256, GS_SMEM>>>(xh, xl, Wb + 6u * 131072, nullptr, Vhb, Vlb, nullptr);
    attn_mma<<<ga, 256, AT_SMEM>>>(Qhb, Qlb, Khb, Klb, Vhb, Vlb, Ohb, Olb, 1);
    gemm_mma<2><<<gg, 256, GS_SMEM>>>(Ohb, Olb, Wb + 7u * 131072, out, nullptr, nullptr, bout1);
}

// round 5
// speedup vs baseline: 1.9976x; 1.0288x over previous
#include <cuda_runtime.h>
#include <cuda_bf16.h>

// ============================================================================
// AxialAttention — bf16x3 HMMA GEMMs + bf16x3 HMMA attention core
// Round 5: pass-major MMA ordering (break accumulator RAW chains),
//          fused QKV projection launch.
// ============================================================================

#define NTOK 131072          // 8*128*128 tokens
#define CDIM 256

// ---- scratch (device globals: allocation-guard safe) ----
__device__ __nv_bfloat16 g_xh[NTOK * CDIM];
__device__ __nv_bfloat16 g_xl[NTOK * CDIM];
__device__ __nv_bfloat16 g_Qh[NTOK * CDIM];
__device__ __nv_bfloat16 g_Ql[NTOK * CDIM];
__device__ __nv_bfloat16 g_Kh[NTOK * CDIM];
__device__ __nv_bfloat16 g_Kl[NTOK * CDIM];
__device__ __nv_bfloat16 g_Vh[NTOK * CDIM];
__device__ __nv_bfloat16 g_Vl[NTOK * CDIM];
__device__ __nv_bfloat16 g_Oh[NTOK * CDIM];
__device__ __nv_bfloat16 g_Ol[NTOK * CDIM];
__device__ __nv_bfloat16 g_Wb[8 * 2 * 65536];   // 8 mats: [hi 256n x 256k][lo ...]

typedef unsigned long long ull;
typedef unsigned int       u32;
typedef unsigned short     u16;

__device__ __forceinline__ u32 smem_u32(const void* p) {
    u32 a;
    asm("{ .reg .u64 t; cvta.to.shared.u64 t, %1; cvt.u32.u64 %0, t; }" : "=r"(a) : "l"(p));
    return a;
}
__device__ __forceinline__ void cpasync16(u32 dst, const void* src) {
    asm volatile("cp.async.cg.shared.global [%0], [%1], 16;" :: "r"(dst), "l"(src));
}
__device__ __forceinline__ void cp_commit() {
    asm volatile("cp.async.commit_group;" ::: "memory");
}
template<int N> __device__ __forceinline__ void cp_wait() {
    asm volatile("cp.async.wait_group %0;" :: "n"(N) : "memory");
}
__device__ __forceinline__ void ldsm4(u32* r, u32 addr) {
    asm volatile("ldmatrix.sync.aligned.m8n8.x4.shared.b16 {%0,%1,%2,%3}, [%4];"
                 : "=r"(r[0]), "=r"(r[1]), "=r"(r[2]), "=r"(r[3]) : "r"(addr));
}
__device__ __forceinline__ void ldsm4t(u32* r, u32 addr) {
    asm volatile("ldmatrix.sync.aligned.m8n8.x4.trans.shared.b16 {%0,%1,%2,%3}, [%4];"
                 : "=r"(r[0]), "=r"(r[1]), "=r"(r[2]), "=r"(r[3]) : "r"(addr));
}
__device__ __forceinline__ void mma16816(float* c, const u32* a, u32 b0, u32 b1) {
    asm volatile(
        "mma.sync.aligned.m16n8k16.row.col.f32.bf16.bf16.f32 "
        "{%0,%1,%2,%3}, {%4,%5,%6,%7}, {%8,%9}, {%0,%1,%2,%3};"
        : "+f"(c[0]), "+f"(c[1]), "+f"(c[2]), "+f"(c[3])
        : "r"(a[0]), "r"(a[1]), "r"(a[2]), "r"(a[3]), "r"(b0), "r"(b1));
}
__device__ __forceinline__ u32 cvt_bf16x2(float hi, float lo) {
    u32 r;
    asm("cvt.rn.satfinite.bf16x2.f32 %0, %1, %2;" : "=r"(r) : "f"(hi), "f"(lo));
    return r;
}

// bf16 hi/lo split
__device__ __forceinline__ void split1(float v, u16& h, u16& l) {
    __nv_bfloat16 hb = __float2bfloat16(v);
    float hf = __bfloat162float(hb);
    __nv_bfloat16 lb = __float2bfloat16(v - hf);
    h = __bfloat16_as_ushort(hb);
    l = __bfloat16_as_ushort(lb);
}
__device__ __forceinline__ void split_pair(float e0, float e1, u32& hw, u32& lw) {
    __nv_bfloat16 h0 = __float2bfloat16(e0);
    __nv_bfloat16 h1 = __float2bfloat16(e1);
    hw = ((u32)__bfloat16_as_ushort(h1) << 16) | (u32)__bfloat16_as_ushort(h0);
    lw = cvt_bf16x2(e1 - __bfloat162float(h1), e0 - __bfloat162float(h0));
}

// ============================================================================
// Prep kernels
// ============================================================================
__global__ void prep_weights(const float* __restrict__ Wq0, const float* __restrict__ Wkv0,
                             const float* __restrict__ Wout0,
                             const float* __restrict__ Wq1, const float* __restrict__ Wkv1,
                             const float* __restrict__ Wout1,
                             __nv_bfloat16* __restrict__ Wb)
{
    const int m = blockIdx.x;      // 0..7 : [q0,k0,v0,o0,q1,k1,v1,o1]
    const int slab = blockIdx.y;   // 0..7
    const float* W;
    int ld = 256, coff = 0;
    float scale = 1.0f;
    switch (m & 3) {
        case 0: W = (m < 4) ? Wq0 : Wq1; scale = 0.17677669529663687f; break;  // 32^-0.5
        case 1: W = (m < 4) ? Wkv0 : Wkv1; ld = 512; break;
        case 2: W = (m < 4) ? Wkv0 : Wkv1; ld = 512; coff = 256; break;
        default: W = (m < 4) ? Wout0 : Wout1; break;
    }
    u16* dh = (u16*)(Wb + (size_t)m * 131072);
    u16* dl = dh + 65536;
    for (int e = threadIdx.x; e < 8192; e += 256) {
        int n = slab * 32 + (e >> 8);
        int k = e & 255;
        float v = W[k * ld + coff + n] * scale;   // B[n][k] = W[k][n]
        u16 h, l; split1(v, h, l);
        dh[n * 256 + k] = h;
        dl[n * 256 + k] = l;
    }
}

__global__ void split_x_kernel(const float* __restrict__ x,
                               __nv_bfloat16* __restrict__ xh,
                               __nv_bfloat16* __restrict__ xl)
{
    size_t i = ((size_t)blockIdx.x * 256 + threadIdx.x) * 4;
    float4 v = *(const float4*)(x + i);
    ushort4 h, l;
    split1(v.x, h.x, l.x); split1(v.y, h.y, l.y);
    split1(v.z, h.z, l.z); split1(v.w, h.w, l.w);
    *(ushort4*)((u16*)xh + i) = h;
    *(ushort4*)((u16*)xl + i) = l;
}

// ============================================================================
// GEMM core: 128m x 128n x 256k, bf16x3, pass-major MMA ordering.
// ============================================================================
#define GS_ROWB   80
#define GS_PART   10240
#define GS_STAGE  40960
#define GS_SMEM   81920

// mainloop shared by all GEMM kernels; acc laid out [mf][nf][4]
__device__ __forceinline__ void gemm_mainloop(
    u32 sb, const __nv_bfloat16* __restrict__ Ah, const __nv_bfloat16* __restrict__ Al,
    const __nv_bfloat16* __restrict__ Bh, const __nv_bfloat16* __restrict__ Bl,
    int rowBase, int colBase, int t, float acc[4][4][4])
{
    const int l = t & 31;
    const int wm = (t >> 5) >> 2;
    const int wn = (t >> 5) & 3;
    const int lr = t >> 2, lc = t & 3;
    const u32 lmOff = (u32)((l & 15) * GS_ROWB + (l >> 4) * 16);

    auto prefetch = [&](int s, int kc) {
        const u32 stb = sb + s * GS_STAGE;
        const int kcol = kc * 32;
#pragma unroll
        for (int i = 0; i < 2; i++) {
            const int r = lr + i * 64;
            const u32 doff = (u32)(r * GS_ROWB + lc * 16);
            const size_t gA = (size_t)(rowBase + r) * 256 + kcol + lc * 8;
            const size_t gB = (size_t)(colBase + r) * 256 + kcol + lc * 8;
            cpasync16(stb + doff,                 Ah + gA);
            cpasync16(stb + GS_PART + doff,       Al + gA);
            cpasync16(stb + 2 * GS_PART + doff,   Bh + gB);
            cpasync16(stb + 3 * GS_PART + doff,   Bl + gB);
        }
        cp_commit();
    };

    prefetch(0, 0);

    for (int kc = 0; kc < 8; kc++) {
        const int s = kc & 1;
        if (kc < 7) prefetch(s ^ 1, kc + 1);
        if (kc < 7) cp_wait<1>(); else cp_wait<0>();
        __syncthreads();

        const u32 stb = sb + s * GS_STAGE;
#pragma unroll
        for (int ks = 0; ks < 2; ks++) {
            u32 ah[4][4], al[4][4];
#pragma unroll
            for (int mf = 0; mf < 4; mf++) {
                const u32 a = stb + (u32)((wm * 64 + mf * 16) * GS_ROWB + ks * 32) + lmOff;
                ldsm4(ah[mf], a);
                ldsm4(al[mf], a + GS_PART);
            }
            u32 bh[2][4], bl[2][4];
#pragma unroll
            for (int g = 0; g < 2; g++) {
                const u32 b = stb + 2 * GS_PART
                            + (u32)((wn * 32 + g * 16) * GS_ROWB + ks * 32) + lmOff;
                ldsm4(bh[g], b);
                ldsm4(bl[g], b + GS_PART);
            }
            // pass-major: 16 independent accumulators between dependent HMMAs
#pragma unroll
            for (int mf = 0; mf < 4; mf++)
#pragma unroll
                for (int nf = 0; nf < 4; nf++)
                    mma16816(acc[mf][nf], ah[mf], bh[nf >> 1][nf & 1], bh[nf >> 1][(nf & 1) + 2]);
#pragma unroll
            for (int mf = 0; mf < 4; mf++)
#pragma unroll
                for (int nf = 0; nf < 4; nf++)
                    mma16816(acc[mf][nf], al[mf], bh[nf >> 1][nf & 1], bh[nf >> 1][(nf & 1) + 2]);
#pragma unroll
            for (int mf = 0; mf < 4; mf++)
#pragma unroll
                for (int nf = 0; nf < 4; nf++)
                    mma16816(acc[mf][nf], ah[mf], bl[nf >> 1][nf & 1], bl[nf >> 1][(nf & 1) + 2]);
        }
        __syncthreads();
    }
}

// ---- fused QKV projection: grid (6, 1024): x -> Q|K|V (bf16 hi/lo out) ----
__global__ void __launch_bounds__(256)
gemm_qkv(const __nv_bfloat16* __restrict__ Ah, const __nv_bfloat16* __restrict__ Al,
         const __nv_bfloat16* __restrict__ Bbase,
         __nv_bfloat16* __restrict__ Qh, __nv_bfloat16* __restrict__ Ql,
         __nv_bfloat16* __restrict__ Kh, __nv_bfloat16* __restrict__ Kl,
         __nv_bfloat16* __restrict__ Vh, __nv_bfloat16* __restrict__ Vl)
{
    extern __shared__ __align__(128) char smem[];
    const u32 sb = smem_u32(smem);
    const int t = threadIdx.x;
    const int bx = blockIdx.x;
    const int mat = bx >> 1;                 // 0=Q 1=K 2=V
    const int colBase = (bx & 1) << 7;
    const int rowBase = blockIdx.y << 7;

    const __nv_bfloat16* Bm = Bbase + (size_t)mat * 131072;
    __nv_bfloat16* Ch = (mat == 0) ? Qh : (mat == 1) ? Kh : Vh;
    __nv_bfloat16* Cl = (mat == 0) ? Ql : (mat == 1) ? Kl : Vl;

    float acc[4][4][4];
#pragma unroll
    for (int i = 0; i < 4; i++)
#pragma unroll
        for (int j = 0; j < 4; j++)
#pragma unroll
            for (int q = 0; q < 4; q++) acc[i][j][q] = 0.f;

    gemm_mainloop(sb, Ah, Al, Bm, Bm + 65536, rowBase, colBase, t, acc);

    const int l = t & 31;
    const int wm = (t >> 5) >> 2, wn = (t >> 5) & 3;
#pragma unroll
    for (int mf = 0; mf < 4; mf++) {
        const int m0 = rowBase + wm * 64 + mf * 16 + (l >> 2);
#pragma unroll
        for (int nf = 0; nf < 4; nf++) {
            const int col = colBase + wn * 32 + nf * 8 + 2 * (l & 3);
            u32 h0, l0, h1, l1;
            split_pair(acc[mf][nf][0], acc[mf][nf][1], h0, l0);
            split_pair(acc[mf][nf][2], acc[mf][nf][3], h1, l1);
            const size_t i0 = (size_t)m0 * 256 + col;
            const size_t i1 = i0 + 8 * 256;
            *(u32*)((u16*)Ch + i0) = h0;
            *(u32*)((u16*)Cl + i0) = l0;
            *(u32*)((u16*)Ch + i1) = h1;
            *(u32*)((u16*)Cl + i1) = l1;
        }
    }
}

// ---- out-projection: f32 out + bias (+accum) ----
template<bool ACCUM>
__global__ void __launch_bounds__(256)
gemm_out(const __nv_bfloat16* __restrict__ Ah, const __nv_bfloat16* __restrict__ Al,
         const __nv_bfloat16* __restrict__ Bm, float* __restrict__ C,
         const float* __restrict__ bias)
{
    extern __shared__ __align__(128) char smem[];
    const u32 sb = smem_u32(smem);
    const int t = threadIdx.x;
    const int rowBase = blockIdx.y << 7;
    const int colBase = blockIdx.x << 7;

    float acc[4][4][4];
#pragma unroll
    for (int i = 0; i < 4; i++)
#pragma unroll
        for (int j = 0; j < 4; j++)
#pragma unroll
            for (int q = 0; q < 4; q++) acc[i][j][q] = 0.f;

    gemm_mainloop(sb, Ah, Al, Bm, Bm + 65536, rowBase, colBase, t, acc);

    const int l = t & 31;
    const int wm = (t >> 5) >> 2, wn = (t >> 5) & 3;
#pragma unroll
    for (int mf = 0; mf < 4; mf++) {
        const int m0 = rowBase + wm * 64 + mf * 16 + (l >> 2);
#pragma unroll
        for (int nf = 0; nf < 4; nf++) {
            const int col = colBase + wn * 32 + nf * 8 + 2 * (l & 3);
            float2 v0 = make_float2(acc[mf][nf][0], acc[mf][nf][1]);
            float2 v1 = make_float2(acc[mf][nf][2], acc[mf][nf][3]);
            float2 b = *(const float2*)(bias + col);
            v0.x += b.x; v0.y += b.y; v1.x += b.x; v1.y += b.y;
            float* p0 = C + (size_t)m0 * 256 + col;
            float* p1 = p0 + 8 * 256;
            if (ACCUM) {
                float2 c0 = *(float2*)p0, c1 = *(float2*)p1;
                v0.x += c0.x; v0.y += c0.y; v1.x += c1.x; v1.y += c1.y;
            }
            *(float2*)p0 = v0;
            *(float2*)p1 = v1;
        }
    }
}

// ============================================================================
// HMMA attention: one block per (sequence, head). seqlen=128, e=32.
// Warp w owns query rows w*16..+15. bf16x3 on S=QK^T and O=PV, pass-major.
// ============================================================================
#define AT_ROWB 80
#define AT_TILE 10240
#define AT_SMEM (6 * AT_TILE)   // 61440

__global__ void __launch_bounds__(256, 2)
attn_mma(const __nv_bfloat16* __restrict__ Qh, const __nv_bfloat16* __restrict__ Ql,
         const __nv_bfloat16* __restrict__ Kh, const __nv_bfloat16* __restrict__ Kl,
         const __nv_bfloat16* __restrict__ Vh, const __nv_bfloat16* __restrict__ Vl,
         __nv_bfloat16* __restrict__ Oh, __nv_bfloat16* __restrict__ Ol, int axis)
{
    extern __shared__ __align__(128) char smem[];
    const u32 sb = smem_u32(smem);
    const int t = threadIdx.x;
    const int l = t & 31;
    const int w = t >> 5;

    const int s = blockIdx.x;
    const int head = blockIdx.y;
    int tokBase, tokStride;
    if (axis == 0) { int b = s >> 7, ww = s & 127; tokBase = b * 16384 + ww; tokStride = 128; }
    else           { tokBase = s * 128; tokStride = 1; }
    const int chanOff = head * 32;

    // ---- load 6 tiles (cp.async, one shot) ----
    {
        const __nv_bfloat16* srcs[6] = { Qh, Ql, Kh, Kl, Vh, Vl };
#pragma unroll
        for (int tile = 0; tile < 6; tile++) {
            const u16* src = (const u16*)srcs[tile];
#pragma unroll
            for (int i = 0; i < 2; i++) {
                const int c = t + i * 256;
                const int row = c >> 2, cg = c & 3;
                const size_t g = (size_t)(tokBase + row * tokStride) * 256 + chanOff + cg * 8;
                cpasync16(sb + tile * AT_TILE + row * AT_ROWB + cg * 16, src + g);
            }
        }
        cp_commit();
        cp_wait<0>();
        __syncthreads();
    }

    const u32 lmOff = (u32)((l & 15) * AT_ROWB + (l >> 4) * 16);

    // ---- S = Q K^T (bf16x3), warp strip rows w*16..+15, full 128 cols ----
    float sv[16][4];
#pragma unroll
    for (int nf = 0; nf < 16; nf++)
#pragma unroll
        for (int q = 0; q < 4; q++) sv[nf][q] = 0.f;

#pragma unroll
    for (int kc = 0; kc < 2; kc++) {
        u32 aqh[4], aql[4];
        const u32 qa = sb + (u32)(w * 16 * AT_ROWB + kc * 32) + lmOff;
        ldsm4(aqh, qa);
        ldsm4(aql, qa + AT_TILE);
#pragma unroll
        for (int gp = 0; gp < 4; gp++) {        // pairs of 16-col groups
            u32 kh4[2][4], kl4[2][4];
#pragma unroll
            for (int gi = 0; gi < 2; gi++) {
                const int g = gp * 2 + gi;
                const u32 ka = sb + 2 * AT_TILE + (u32)(g * 16 * AT_ROWB + kc * 32) + lmOff;
                ldsm4(kh4[gi], ka);
                ldsm4(kl4[gi], ka + AT_TILE);
            }
            // pass-major over 4 positions (gi, j)
#pragma unroll
            for (int gi = 0; gi < 2; gi++)
#pragma unroll
                for (int j = 0; j < 2; j++)
                    mma16816(sv[(gp * 2 + gi) * 2 + j], aqh, kh4[gi][j], kh4[gi][j + 2]);
#pragma unroll
            for (int gi = 0; gi < 2; gi++)
#pragma unroll
                for (int j = 0; j < 2; j++)
                    mma16816(sv[(gp * 2 + gi) * 2 + j], aql, kh4[gi][j], kh4[gi][j + 2]);
#pragma unroll
            for (int gi = 0; gi < 2; gi++)
#pragma unroll
                for (int j = 0; j < 2; j++)
                    mma16816(sv[(gp * 2 + gi) * 2 + j], aqh, kl4[gi][j], kl4[gi][j + 2]);
        }
    }

    // ---- softmax (rows fully in-warp: quad shuffles only) ----
    float mx0 = -1e30f, mx1 = -1e30f;
#pragma unroll
    for (int nf = 0; nf < 16; nf++) {
        mx0 = fmaxf(mx0, fmaxf(sv[nf][0], sv[nf][1]));
        mx1 = fmaxf(mx1, fmaxf(sv[nf][2], sv[nf][3]));
    }
    mx0 = fmaxf(mx0, __shfl_xor_sync(0xffffffffu, mx0, 1));
    mx0 = fmaxf(mx0, __shfl_xor_sync(0xffffffffu, mx0, 2));
    mx1 = fmaxf(mx1, __shfl_xor_sync(0xffffffffu, mx1, 1));
    mx1 = fmaxf(mx1, __shfl_xor_sync(0xffffffffu, mx1, 2));

    float sum0 = 0.f, sum1 = 0.f;
#pragma unroll
    for (int nf = 0; nf < 16; nf++) {
        sv[nf][0] = __expf(sv[nf][0] - mx0);
        sv[nf][1] = __expf(sv[nf][1] - mx0);
        sv[nf][2] = __expf(sv[nf][2] - mx1);
        sv[nf][3] = __expf(sv[nf][3] - mx1);
        sum0 += sv[nf][0] + sv[nf][1];
        sum1 += sv[nf][2] + sv[nf][3];
    }
    sum0 += __shfl_xor_sync(0xffffffffu, sum0, 1);
    sum0 += __shfl_xor_sync(0xffffffffu, sum0, 2);
    sum1 += __shfl_xor_sync(0xffffffffu, sum1, 1);
    sum1 += __shfl_xor_sync(0xffffffffu, sum1, 2);
    const float inv0 = 1.0f / sum0;
    const float inv1 = 1.0f / sum1;

    // ---- O = P V (bf16x3), pass-major; P frags built in-register ----
    float ao[4][4];
#pragma unroll
    for (int nf = 0; nf < 4; nf++)
#pragma unroll
        for (int q = 0; q < 4; q++) ao[nf][q] = 0.f;

#pragma unroll
    for (int jc = 0; jc < 8; jc++) {
        u32 ph[4], pl[4];
        split_pair(sv[2 * jc][0],     sv[2 * jc][1],     ph[0], pl[0]);
        split_pair(sv[2 * jc][2],     sv[2 * jc][3],     ph[1], pl[1]);
        split_pair(sv[2 * jc + 1][0], sv[2 * jc + 1][1], ph[2], pl[2]);
        split_pair(sv[2 * jc + 1][2], sv[2 * jc + 1][3], ph[3], pl[3]);
        u32 vh4[2][4], vl4[2][4];
#pragma unroll
        for (int eg = 0; eg < 2; eg++) {
            const u32 va = sb + 4 * AT_TILE + (u32)(jc * 16 * AT_ROWB + eg * 32) + lmOff;
            ldsm4t(vh4[eg], va);
            ldsm4t(vl4[eg], va + AT_TILE);
        }
#pragma unroll
        for (int eg = 0; eg < 2; eg++)
#pragma unroll
            for (int j = 0; j < 2; j++)
                mma16816(ao[eg * 2 + j], ph, vh4[eg][j * 2], vh4[eg][j * 2 + 1]);
#pragma unroll
        for (int eg = 0; eg < 2; eg++)
#pragma unroll
            for (int j = 0; j < 2; j++)
                mma16816(ao[eg * 2 + j], pl, vh4[eg][j * 2], vh4[eg][j * 2 + 1]);
#pragma unroll
        for (int eg = 0; eg < 2; eg++)
#pragma unroll
            for (int j = 0; j < 2; j++)
                mma16816(ao[eg * 2 + j], ph, vl4[eg][j * 2], vl4[eg][j * 2 + 1]);
    }

    // ---- normalize + write bf16 hi/lo ----
    const int row0 = w * 16 + (l >> 2);
    const int row1 = row0 + 8;
    const size_t tok0 = (size_t)(tokBase + row0 * tokStride) * 256;
    const size_t tok1 = (size_t)(tokBase + row1 * tokStride) * 256;
#pragma unroll
    for (int nf = 0; nf < 4; nf++) {
        const int col = chanOff + nf * 8 + 2 * (l & 3);
        u32 h0, l0, h1, l1;
        split_pair(ao[nf][0] * inv0, ao[nf][1] * inv0, h0, l0);
        split_pair(ao[nf][2] * inv1, ao[nf][3] * inv1, h1, l1);
        *(u32*)((u16*)Oh + tok0 + col) = h0;
        *(u32*)((u16*)Ol + tok0 + col) = l0;
        *(u32*)((u16*)Oh + tok1 + col) = h1;
        *(u32*)((u16*)Ol + tok1 + col) = l1;
    }
}

// ============================================================================
// Host launcher
// ============================================================================
extern "C" void kernel_launch(void* const* d_in, const int* in_sizes, int n_in,
                              void* d_out, int out_size)
{
    (void)in_sizes; (void)n_in; (void)out_size;
    const float* x     = (const float*)d_in[0];
    const float* Wq0   = (const float*)d_in[1];
    const float* Wkv0  = (const float*)d_in[2];
    const float* Wout0 = (const float*)d_in[3];
    const float* bout0 = (const float*)d_in[4];
    const float* Wq1   = (const float*)d_in[5];
    const float* Wkv1  = (const float*)d_in[6];
    const float* Wout1 = (const float*)d_in[7];
    const float* bout1 = (const float*)d_in[8];
    float* out = (float*)d_out;

    __nv_bfloat16 *xh, *xl, *Qhb, *Qlb, *Khb, *Klb, *Vhb, *Vlb, *Ohb, *Olb, *Wb;
    cudaGetSymbolAddress((void**)&xh,  g_xh);
    cudaGetSymbolAddress((void**)&xl,  g_xl);
    cudaGetSymbolAddress((void**)&Qhb, g_Qh);
    cudaGetSymbolAddress((void**)&Qlb, g_Ql);
    cudaGetSymbolAddress((void**)&Khb, g_Kh);
    cudaGetSymbolAddress((void**)&Klb, g_Kl);
    cudaGetSymbolAddress((void**)&Vhb, g_Vh);
    cudaGetSymbolAddress((void**)&Vlb, g_Vl);
    cudaGetSymbolAddress((void**)&Ohb, g_Oh);
    cudaGetSymbolAddress((void**)&Olb, g_Ol);
    cudaGetSymbolAddress((void**)&Wb,  g_Wb);

    cudaFuncSetAttribute(gemm_qkv,
                         cudaFuncAttributeMaxDynamicSharedMemorySize, GS_SMEM);
    cudaFuncSetAttribute(gemm_out<false>,
                         cudaFuncAttributeMaxDynamicSharedMemorySize, GS_SMEM);
    cudaFuncSetAttribute(gemm_out<true>,
                         cudaFuncAttributeMaxDynamicSharedMemorySize, GS_SMEM);
    cudaFuncSetAttribute(attn_mma,
                         cudaFuncAttributeMaxDynamicSharedMemorySize, AT_SMEM);

    const dim3 gq(6, 1024);    // fused QKV: (mat*2 + ntile, m tiles)
    const dim3 gg(2, 1024);    // out-proj
    const dim3 ga(1024, 8);    // (sequences, heads)

    prep_weights<<<dim3(8, 8), 256>>>(Wq0, Wkv0, Wout0, Wq1, Wkv1, Wout1, Wb);
    split_x_kernel<<<32768, 256>>>(x, xh, xl);

    // ---- axis 0 ----
    gemm_qkv<<<gq, 256, GS_SMEM>>>(xh, xl, Wb, Qhb, Qlb, Khb, Klb, Vhb, Vlb);
    attn_mma<<<ga, 256, AT_SMEM>>>(Qhb, Qlb, Khb, Klb, Vhb, Vlb, Ohb, Olb, 0);
    gemm_out<false><<<gg, 256, GS_SMEM>>>(Ohb, Olb, Wb + 3u * 131072, out, bout0);

    // ---- axis 1 ----
    gemm_qkv<<<gq, 256, GS_SMEM>>>(xh, xl, Wb + 4u * 131072, Qhb, Qlb, Khb, Klb, Vhb, Vlb);
    attn_mma<<<ga, 256, AT_SMEM>>>(Qhb, Qlb, Khb, Klb, Vhb, Vlb, Ohb, Olb, 1);
    gemm_out<true><<<gg, 256, GS_SMEM>>>(Ohb, Olb, Wb + 7u * 131072, out, bout1);
}

// round 6
// speedup vs baseline: 2.7135x; 1.3584x over previous
#include <cuda_runtime.h>
#include <cuda_fp16.h>

// ============================================================================
// AxialAttention — fp16x2 asymmetric-split HMMA (A=hi+lo, B=hi only)
// GEMMs + attention all on mma.sync m16n8k16 f16->f32.
// ============================================================================

#define NTOK 131072          // 8*128*128 tokens

// ---- scratch (device globals: allocation-guard safe) ----
__device__ __half g_xh[NTOK * 256];
__device__ __half g_xl[NTOK * 256];
__device__ __half g_Qh[NTOK * 256];
__device__ __half g_Ql[NTOK * 256];
__device__ __half g_Kh[NTOK * 256];
__device__ __half g_Vh[NTOK * 256];
__device__ __half g_Oh[NTOK * 256];
__device__ __half g_Ol[NTOK * 256];
__device__ __half g_Wh[8 * 65536];     // 8 mats hi-only, [n][k] 256x256

typedef unsigned long long ull;
typedef unsigned int       u32;
typedef unsigned short     u16;

__device__ __forceinline__ u32 smem_u32(const void* p) {
    u32 a;
    asm("{ .reg .u64 t; cvta.to.shared.u64 t, %1; cvt.u32.u64 %0, t; }" : "=r"(a) : "l"(p));
    return a;
}
__device__ __forceinline__ void cpasync16(u32 dst, const void* src) {
    asm volatile("cp.async.cg.shared.global [%0], [%1], 16;" :: "r"(dst), "l"(src));
}
__device__ __forceinline__ void cp_commit() {
    asm volatile("cp.async.commit_group;" ::: "memory");
}
template<int N> __device__ __forceinline__ void cp_wait() {
    asm volatile("cp.async.wait_group %0;" :: "n"(N) : "memory");
}
__device__ __forceinline__ void ldsm4(u32* r, u32 addr) {
    asm volatile("ldmatrix.sync.aligned.m8n8.x4.shared.b16 {%0,%1,%2,%3}, [%4];"
                 : "=r"(r[0]), "=r"(r[1]), "=r"(r[2]), "=r"(r[3]) : "r"(addr));
}
__device__ __forceinline__ void ldsm4t(u32* r, u32 addr) {
    asm volatile("ldmatrix.sync.aligned.m8n8.x4.trans.shared.b16 {%0,%1,%2,%3}, [%4];"
                 : "=r"(r[0]), "=r"(r[1]), "=r"(r[2]), "=r"(r[3]) : "r"(addr));
}
__device__ __forceinline__ void mma16816(float* c, const u32* a, u32 b0, u32 b1) {
    asm volatile(
        "mma.sync.aligned.m16n8k16.row.col.f32.f16.f16.f32 "
        "{%0,%1,%2,%3}, {%4,%5,%6,%7}, {%8,%9}, {%0,%1,%2,%3};"
        : "+f"(c[0]), "+f"(c[1]), "+f"(c[2]), "+f"(c[3])
        : "r"(a[0]), "r"(a[1]), "r"(a[2]), "r"(a[3]), "r"(b0), "r"(b1));
}
__device__ __forceinline__ u32 cvt_f16x2(float hi, float lo) {
    u32 r;
    asm("cvt.rn.f16x2.f32 %0, %1, %2;" : "=r"(r) : "f"(hi), "f"(lo));
    return r;
}
__device__ __forceinline__ u32 pack_h2(float e0, float e1) {
    return cvt_f16x2(e1, e0);     // e0 -> low half, e1 -> high half
}
// split a pair into hi word + lo (residual) word
__device__ __forceinline__ void split_pair(float e0, float e1, u32& hw, u32& lw) {
    __half h0 = __float2half_rn(e0);
    __half h1 = __float2half_rn(e1);
    hw = ((u32)__half_as_ushort(h1) << 16) | (u32)__half_as_ushort(h0);
    lw = cvt_f16x2(e1 - __half2float(h1), e0 - __half2float(h0));
}
__device__ __forceinline__ void split1(float v, u16& h, u16& l) {
    __half hb = __float2half_rn(v);
    h = __half_as_ushort(hb);
    l = __half_as_ushort(__float2half_rn(v - __half2float(hb)));
}

// ============================================================================
// Prep kernels
// ============================================================================
__global__ void prep_weights(const float* __restrict__ Wq0, const float* __restrict__ Wkv0,
                             const float* __restrict__ Wout0,
                             const float* __restrict__ Wq1, const float* __restrict__ Wkv1,
                             const float* __restrict__ Wout1,
                             __half* __restrict__ Wh)
{
    const int m = blockIdx.x;      // 0..7 : [q0,k0,v0,o0,q1,k1,v1,o1]
    const int slab = blockIdx.y;   // 0..7
    const float* W;
    int ld = 256, coff = 0;
    float scale = 1.0f;
    switch (m & 3) {
        case 0: W = (m < 4) ? Wq0 : Wq1; scale = 0.17677669529663687f; break;  // 32^-0.5
        case 1: W = (m < 4) ? Wkv0 : Wkv1; ld = 512; break;
        case 2: W = (m < 4) ? Wkv0 : Wkv1; ld = 512; coff = 256; break;
        default: W = (m < 4) ? Wout0 : Wout1; break;
    }
    __half* dh = Wh + (size_t)m * 65536;
    for (int e = threadIdx.x; e < 8192; e += 256) {
        int n = slab * 32 + (e >> 8);
        int k = e & 255;
        dh[n * 256 + k] = __float2half_rn(W[k * ld + coff + n] * scale);  // B[n][k]=W[k][n]
    }
}

__global__ void split_x_kernel(const float* __restrict__ x,
                               __half* __restrict__ xh, __half* __restrict__ xl)
{
    size_t i = ((size_t)blockIdx.x * 256 + threadIdx.x) * 4;
    float4 v = *(const float4*)(x + i);
    ushort4 h, l;
    split1(v.x, h.x, l.x); split1(v.y, h.y, l.y);
    split1(v.z, h.z, l.z); split1(v.w, h.w, l.w);
    *(ushort4*)((u16*)xh + i) = h;
    *(ushort4*)((u16*)xl + i) = l;
}

// ============================================================================
// GEMM core: 128m x 128n x 256k, fp16x2 (AhBh + AlBh), 3-stage cp.async,
// one __syncthreads per k-chunk, pass-major MMA ordering.
// smem stage: Ah | Al | Bh, each 128 rows x 32 k, 80B row stride.
// ============================================================================
#define GS_ROWB   80
#define GS_PART   10240
#define GS_STAGE  30720
#define GS_SMEM   92160     // 3 stages

__device__ __forceinline__ void gemm_mainloop(
    u32 sb, const __half* __restrict__ Ah, const __half* __restrict__ Al,
    const __half* __restrict__ Bh,
    int rowBase, int colBase, int t, float acc[4][4][4])
{
    const int l = t & 31;
    const int wm = (t >> 5) >> 2;
    const int wn = (t >> 5) & 3;
    const int lr = t >> 2, lc = t & 3;
    const u32 lmOff = (u32)((l & 15) * GS_ROWB + (l >> 4) * 16);

    auto prefetch = [&](int kc) {
        const u32 stb = sb + (u32)(kc % 3) * GS_STAGE;
        const int kcol = kc * 32;
#pragma unroll
        for (int i = 0; i < 2; i++) {
            const int r = lr + i * 64;
            const u32 doff = (u32)(r * GS_ROWB + lc * 16);
            const size_t gA = (size_t)(rowBase + r) * 256 + kcol + lc * 8;
            const size_t gB = (size_t)(colBase + r) * 256 + kcol + lc * 8;
            cpasync16(stb + doff,               Ah + gA);
            cpasync16(stb + GS_PART + doff,     Al + gA);
            cpasync16(stb + 2 * GS_PART + doff, Bh + gB);
        }
        cp_commit();
    };

    prefetch(0);
    prefetch(1);

    for (int kc = 0; kc < 8; kc++) {
        if (kc < 7) cp_wait<1>(); else cp_wait<0>();
        __syncthreads();
        if (kc < 6) prefetch(kc + 2);

        const u32 stb = sb + (u32)(kc % 3) * GS_STAGE;
#pragma unroll
        for (int ks = 0; ks < 2; ks++) {
            u32 ah[4][4], al[4][4];
#pragma unroll
            for (int mf = 0; mf < 4; mf++) {
                const u32 a = stb + (u32)((wm * 64 + mf * 16) * GS_ROWB + ks * 32) + lmOff;
                ldsm4(ah[mf], a);
                ldsm4(al[mf], a + GS_PART);
            }
            u32 bh[2][4];
#pragma unroll
            for (int g = 0; g < 2; g++) {
                const u32 b = stb + 2 * GS_PART
                            + (u32)((wn * 32 + g * 16) * GS_ROWB + ks * 32) + lmOff;
                ldsm4(bh[g], b);
            }
            // pass-major: 16 independent accumulators between dependent HMMAs
#pragma unroll
            for (int mf = 0; mf < 4; mf++)
#pragma unroll
                for (int nf = 0; nf < 4; nf++)
                    mma16816(acc[mf][nf], ah[mf], bh[nf >> 1][nf & 1], bh[nf >> 1][(nf & 1) + 2]);
#pragma unroll
            for (int mf = 0; mf < 4; mf++)
#pragma unroll
                for (int nf = 0; nf < 4; nf++)
                    mma16816(acc[mf][nf], al[mf], bh[nf >> 1][nf & 1], bh[nf >> 1][(nf & 1) + 2]);
        }
    }
}

// ---- fused QKV projection: grid (6, 1024) ----
// Q output: hi+lo (A-side of S).  K, V outputs: hi only (B-side operands).
__global__ void __launch_bounds__(256)
gemm_qkv(const __half* __restrict__ Ah, const __half* __restrict__ Al,
         const __half* __restrict__ Bbase,
         __half* __restrict__ Qh, __half* __restrict__ Ql,
         __half* __restrict__ Kh, __half* __restrict__ Vh)
{
    extern __shared__ __align__(128) char smem[];
    const u32 sb = smem_u32(smem);
    const int t = threadIdx.x;
    const int bx = blockIdx.x;
    const int mat = bx >> 1;                 // 0=Q 1=K 2=V
    const int colBase = (bx & 1) << 7;
    const int rowBase = blockIdx.y << 7;

    const __half* Bm = Bbase + (size_t)mat * 65536;

    float acc[4][4][4];
#pragma unroll
    for (int i = 0; i < 4; i++)
#pragma unroll
        for (int j = 0; j < 4; j++)
#pragma unroll
            for (int q = 0; q < 4; q++) acc[i][j][q] = 0.f;

    gemm_mainloop(sb, Ah, Al, Bm, rowBase, colBase, t, acc);

    const int l = t & 31;
    const int wm = (t >> 5) >> 2, wn = (t >> 5) & 3;
#pragma unroll
    for (int mf = 0; mf < 4; mf++) {
        const int m0 = rowBase + wm * 64 + mf * 16 + (l >> 2);
#pragma unroll
        for (int nf = 0; nf < 4; nf++) {
            const int col = colBase + wn * 32 + nf * 8 + 2 * (l & 3);
            const size_t i0 = (size_t)m0 * 256 + col;
            const size_t i1 = i0 + 8 * 256;
            if (mat == 0) {
                u32 h0, l0, h1, l1;
                split_pair(acc[mf][nf][0], acc[mf][nf][1], h0, l0);
                split_pair(acc[mf][nf][2], acc[mf][nf][3], h1, l1);
                *(u32*)((u16*)Qh + i0) = h0;
                *(u32*)((u16*)Ql + i0) = l0;
                *(u32*)((u16*)Qh + i1) = h1;
                *(u32*)((u16*)Ql + i1) = l1;
            } else {
                __half* Ch = (mat == 1) ? Kh : Vh;
                *(u32*)((u16*)Ch + i0) = pack_h2(acc[mf][nf][0], acc[mf][nf][1]);
                *(u32*)((u16*)Ch + i1) = pack_h2(acc[mf][nf][2], acc[mf][nf][3]);
            }
        }
    }
}

// ---- out-projection: f32 out + bias (+accum) ----
template<bool ACCUM>
__global__ void __launch_bounds__(256)
gemm_out(const __half* __restrict__ Ah, const __half* __restrict__ Al,
         const __half* __restrict__ Bm, float* __restrict__ C,
         const float* __restrict__ bias)
{
    extern __shared__ __align__(128) char smem[];
    const u32 sb = smem_u32(smem);
    const int t = threadIdx.x;
    const int rowBase = blockIdx.y << 7;
    const int colBase = blockIdx.x << 7;

    float acc[4][4][4];
#pragma unroll
    for (int i = 0; i < 4; i++)
#pragma unroll
        for (int j = 0; j < 4; j++)
#pragma unroll
            for (int q = 0; q < 4; q++) acc[i][j][q] = 0.f;

    gemm_mainloop(sb, Ah, Al, Bm, rowBase, colBase, t, acc);

    const int l = t & 31;
    const int wm = (t >> 5) >> 2, wn = (t >> 5) & 3;
#pragma unroll
    for (int mf = 0; mf < 4; mf++) {
        const int m0 = rowBase + wm * 64 + mf * 16 + (l >> 2);
#pragma unroll
        for (int nf = 0; nf < 4; nf++) {
            const int col = colBase + wn * 32 + nf * 8 + 2 * (l & 3);
            float2 v0 = make_float2(acc[mf][nf][0], acc[mf][nf][1]);
            float2 v1 = make_float2(acc[mf][nf][2], acc[mf][nf][3]);
            float2 b = *(const float2*)(bias + col);
            v0.x += b.x; v0.y += b.y; v1.x += b.x; v1.y += b.y;
            float* p0 = C + (size_t)m0 * 256 + col;
            float* p1 = p0 + 8 * 256;
            if (ACCUM) {
                float2 c0 = *(float2*)p0, c1 = *(float2*)p1;
                v0.x += c0.x; v0.y += c0.y; v1.x += c1.x; v1.y += c1.y;
            }
            *(float2*)p0 = v0;
            *(float2*)p1 = v1;
        }
    }
}

// ============================================================================
// HMMA attention: one block per (sequence, head). seqlen=128, e=32.
// Warp w owns query rows w*16..+15. fp16x2: S = QhKh + QlKh; O = PhVh + PlVh.
// smem tiles: Qh | Ql | Kh | Vh, each 128 rows x 32 chan, 80B row stride.
// ============================================================================
#define AT_ROWB 80
#define AT_TILE 10240
#define AT_SMEM (4 * AT_TILE)   // 40960

__global__ void __launch_bounds__(256, 2)
attn_mma(const __half* __restrict__ Qh, const __half* __restrict__ Ql,
         const __half* __restrict__ Kh, const __half* __restrict__ Vh,
         __half* __restrict__ Oh, __half* __restrict__ Ol, int axis)
{
    extern __shared__ __align__(128) char smem[];
    const u32 sb = smem_u32(smem);
    const int t = threadIdx.x;
    const int l = t & 31;
    const int w = t >> 5;

    const int s = blockIdx.x;
    const int head = blockIdx.y;
    int tokBase, tokStride;
    if (axis == 0) { int b = s >> 7, ww = s & 127; tokBase = b * 16384 + ww; tokStride = 128; }
    else           { tokBase = s * 128; tokStride = 1; }
    const int chanOff = head * 32;

    // ---- load 4 tiles (cp.async, one shot) ----
    {
        const __half* srcs[4] = { Qh, Ql, Kh, Vh };
#pragma unroll
        for (int tile = 0; tile < 4; tile++) {
            const u16* src = (const u16*)srcs[tile];
#pragma unroll
            for (int i = 0; i < 2; i++) {
                const int c = t + i * 256;
                const int row = c >> 2, cg = c & 3;
                const size_t g = (size_t)(tokBase + row * tokStride) * 256 + chanOff + cg * 8;
                cpasync16(sb + tile * AT_TILE + row * AT_ROWB + cg * 16, src + g);
            }
        }
        cp_commit();
        cp_wait<0>();
        __syncthreads();
    }

    const u32 lmOff = (u32)((l & 15) * AT_ROWB + (l >> 4) * 16);

    // ---- S = Q K^T (fp16x2), warp strip rows w*16..+15, full 128 cols ----
    float sv[16][4];
#pragma unroll
    for (int nf = 0; nf < 16; nf++)
#pragma unroll
        for (int q = 0; q < 4; q++) sv[nf][q] = 0.f;

#pragma unroll
    for (int kc = 0; kc < 2; kc++) {
        u32 aqh[4], aql[4];
        const u32 qa = sb + (u32)(w * 16 * AT_ROWB + kc * 32) + lmOff;
        ldsm4(aqh, qa);
        ldsm4(aql, qa + AT_TILE);
#pragma unroll
        for (int gp = 0; gp < 4; gp++) {        // pairs of 16-col groups
            u32 kh4[2][4];
#pragma unroll
            for (int gi = 0; gi < 2; gi++) {
                const int g = gp * 2 + gi;
                const u32 ka = sb + 2 * AT_TILE + (u32)(g * 16 * AT_ROWB + kc * 32) + lmOff;
                ldsm4(kh4[gi], ka);
            }
#pragma unroll
            for (int gi = 0; gi < 2; gi++)
#pragma unroll
                for (int j = 0; j < 2; j++)
                    mma16816(sv[(gp * 2 + gi) * 2 + j], aqh, kh4[gi][j], kh4[gi][j + 2]);
#pragma unroll
            for (int gi = 0; gi < 2; gi++)
#pragma unroll
                for (int j = 0; j < 2; j++)
                    mma16816(sv[(gp * 2 + gi) * 2 + j], aql, kh4[gi][j], kh4[gi][j + 2]);
        }
    }

    // ---- softmax (rows fully in-warp: quad shuffles only) ----
    float mx0 = -1e30f, mx1 = -1e30f;
#pragma unroll
    for (int nf = 0; nf < 16; nf++) {
        mx0 = fmaxf(mx0, fmaxf(sv[nf][0], sv[nf][1]));
        mx1 = fmaxf(mx1, fmaxf(sv[nf][2], sv[nf][3]));
    }
    mx0 = fmaxf(mx0, __shfl_xor_sync(0xffffffffu, mx0, 1));
    mx0 = fmaxf(mx0, __shfl_xor_sync(0xffffffffu, mx0, 2));
    mx1 = fmaxf(mx1, __shfl_xor_sync(0xffffffffu, mx1, 1));
    mx1 = fmaxf(mx1, __shfl_xor_sync(0xffffffffu, mx1, 2));

    float sum0 = 0.f, sum1 = 0.f;
#pragma unroll
    for (int nf = 0; nf < 16; nf++) {
        sv[nf][0] = __expf(sv[nf][0] - mx0);
        sv[nf][1] = __expf(sv[nf][1] - mx0);
        sv[nf][2] = __expf(sv[nf][2] - mx1);
        sv[nf][3] = __expf(sv[nf][3] - mx1);
        sum0 += sv[nf][0] + sv[nf][1];
        sum1 += sv[nf][2] + sv[nf][3];
    }
    sum0 += __shfl_xor_sync(0xffffffffu, sum0, 1);
    sum0 += __shfl_xor_sync(0xffffffffu, sum0, 2);
    sum1 += __shfl_xor_sync(0xffffffffu, sum1, 1);
    sum1 += __shfl_xor_sync(0xffffffffu, sum1, 2);
    const float inv0 = 1.0f / sum0;
    const float inv1 = 1.0f / sum1;

    // ---- O = P V (fp16x2), pass-major; P frags built in-register ----
    float ao[4][4];
#pragma unroll
    for (int nf = 0; nf < 4; nf++)
#pragma unroll
        for (int q = 0; q < 4; q++) ao[nf][q] = 0.f;

#pragma unroll
    for (int jc = 0; jc < 8; jc++) {
        u32 ph[4], pl[4];
        split_pair(sv[2 * jc][0],     sv[2 * jc][1],     ph[0], pl[0]);
        split_pair(sv[2 * jc][2],     sv[2 * jc][3],     ph[1], pl[1]);
        split_pair(sv[2 * jc + 1][0], sv[2 * jc + 1][1], ph[2], pl[2]);
        split_pair(sv[2 * jc + 1][2], sv[2 * jc + 1][3], ph[3], pl[3]);
        u32 vh4[2][4];
#pragma unroll
        for (int eg = 0; eg < 2; eg++) {
            const u32 va = sb + 3 * AT_TILE + (u32)(jc * 16 * AT_ROWB + eg * 32) + lmOff;
            ldsm4t(vh4[eg], va);
        }
#pragma unroll
        for (int eg = 0; eg < 2; eg++)
#pragma unroll
            for (int j = 0; j < 2; j++)
                mma16816(ao[eg * 2 + j], ph, vh4[eg][j * 2], vh4[eg][j * 2 + 1]);
#pragma unroll
        for (int eg = 0; eg < 2; eg++)
#pragma unroll
            for (int j = 0; j < 2; j++)
                mma16816(ao[eg * 2 + j], pl, vh4[eg][j * 2], vh4[eg][j * 2 + 1]);
    }

    // ---- normalize + write fp16 hi/lo ----
    const int row0 = w * 16 + (l >> 2);
    const int row1 = row0 + 8;
    const size_t tok0 = (size_t)(tokBase + row0 * tokStride) * 256;
    const size_t tok1 = (size_t)(tokBase + row1 * tokStride) * 256;
#pragma unroll
    for (int nf = 0; nf < 4; nf++) {
        const int col = chanOff + nf * 8 + 2 * (l & 3);
        u32 h0, l0, h1, l1;
        split_pair(ao[nf][0] * inv0, ao[nf][1] * inv0, h0, l0);
        split_pair(ao[nf][2] * inv1, ao[nf][3] * inv1, h1, l1);
        *(u32*)((u16*)Oh + tok0 + col) = h0;
        *(u32*)((u16*)Ol + tok0 + col) = l0;
        *(u32*)((u16*)Oh + tok1 + col) = h1;
        *(u32*)((u16*)Ol + tok1 + col) = l1;
    }
}

// ============================================================================
// Host launcher
// ============================================================================
extern "C" void kernel_launch(void* const* d_in, const int* in_sizes, int n_in,
                              void* d_out, int out_size)
{
    (void)in_sizes; (void)n_in; (void)out_size;
    const float* x     = (const float*)d_in[0];
    const float* Wq0   = (const float*)d_in[1];
    const float* Wkv0  = (const float*)d_in[2];
    const float* Wout0 = (const float*)d_in[3];
    const float* bout0 = (const float*)d_in[4];
    const float* Wq1   = (const float*)d_in[5];
    const float* Wkv1  = (const float*)d_in[6];
    const float* Wout1 = (const float*)d_in[7];
    const float* bout1 = (const float*)d_in[8];
    float* out = (float*)d_out;

    __half *xh, *xl, *Qhb, *Qlb, *Khb, *Vhb, *Ohb, *Olb, *Wh;
    cudaGetSymbolAddress((void**)&xh,  g_xh);
    cudaGetSymbolAddress((void**)&xl,  g_xl);
    cudaGetSymbolAddress((void**)&Qhb, g_Qh);
    cudaGetSymbolAddress((void**)&Qlb, g_Ql);
    cudaGetSymbolAddress((void**)&Khb, g_Kh);
    cudaGetSymbolAddress((void**)&Vhb, g_Vh);
    cudaGetSymbolAddress((void**)&Ohb, g_Oh);
    cudaGetSymbolAddress((void**)&Olb, g_Ol);
    cudaGetSymbolAddress((void**)&Wh,  g_Wh);

    cudaFuncSetAttribute(gemm_qkv,
                         cudaFuncAttributeMaxDynamicSharedMemorySize, GS_SMEM);
    cudaFuncSetAttribute(gemm_out<false>,
                         cudaFuncAttributeMaxDynamicSharedMemorySize, GS_SMEM);
    cudaFuncSetAttribute(gemm_out<true>,
                         cudaFuncAttributeMaxDynamicSharedMemorySize, GS_SMEM);
    cudaFuncSetAttribute(attn_mma,
                         cudaFuncAttributeMaxDynamicSharedMemorySize, AT_SMEM);

    const dim3 gq(6, 1024);    // fused QKV: (mat*2 + ntile, m tiles)
    const dim3 gg(2, 1024);    // out-proj
    const dim3 ga(1024, 8);    // (sequences, heads)

    prep_weights<<<dim3(8, 8), 256>>>(Wq0, Wkv0, Wout0, Wq1, Wkv1, Wout1, Wh);
    split_x_kernel<<<32768, 256>>>(x, xh, xl);

    // ---- axis 0 ----
    gemm_qkv<<<gq, 256, GS_SMEM>>>(xh, xl, Wh, Qhb, Qlb, Khb, Vhb);
    attn_mma<<<ga, 256, AT_SMEM>>>(Qhb, Qlb, Khb, Vhb, Ohb, Olb, 0);
    gemm_out<false><<<gg, 256, GS_SMEM>>>(Ohb, Olb, Wh + 3u * 65536, out, bout0);

    // ---- axis 1 ----
    gemm_qkv<<<gq, 256, GS_SMEM>>>(xh, xl, Wh + 4u * 65536, Qhb, Qlb, Khb, Vhb);
    attn_mma<<<ga, 256, AT_SMEM>>>(Qhb, Qlb, Khb, Vhb, Ohb, Olb, 1);
    gemm_out<true><<<gg, 256, GS_SMEM>>>(Ohb, Olb, Wh + 7u * 65536, out, bout1);
}

// round 7
// speedup vs baseline: 4.5034x; 1.6596x over previous
#include <cuda_runtime.h>
#include <cuda_fp16.h>

// ============================================================================
// AxialAttention — pure fp16 HMMA (single pass), calibrated-error design.
// GEMMs + attention on mma.sync m16n8k16 f16->f32.
// ============================================================================

#define NTOK 131072          // 8*128*128 tokens

// ---- scratch (device globals: allocation-guard safe) ----
__device__ __half g_xh[NTOK * 256];
__device__ __half g_Qh[NTOK * 256];
__device__ __half g_Kh[NTOK * 256];
__device__ __half g_Vh[NTOK * 256];
__device__ __half g_Oh[NTOK * 256];
__device__ __half g_Wh[8 * 65536];     // 8 mats, [n][k] 256x256

typedef unsigned long long ull;
typedef unsigned int       u32;
typedef unsigned short     u16;

__device__ __forceinline__ u32 smem_u32(const void* p) {
    u32 a;
    asm("{ .reg .u64 t; cvta.to.shared.u64 t, %1; cvt.u32.u64 %0, t; }" : "=r"(a) : "l"(p));
    return a;
}
__device__ __forceinline__ void cpasync16(u32 dst, const void* src) {
    asm volatile("cp.async.cg.shared.global [%0], [%1], 16;" :: "r"(dst), "l"(src));
}
__device__ __forceinline__ void cp_commit() {
    asm volatile("cp.async.commit_group;" ::: "memory");
}
template<int N> __device__ __forceinline__ void cp_wait() {
    asm volatile("cp.async.wait_group %0;" :: "n"(N) : "memory");
}
__device__ __forceinline__ void ldsm4(u32* r, u32 addr) {
    asm volatile("ldmatrix.sync.aligned.m8n8.x4.shared.b16 {%0,%1,%2,%3}, [%4];"
                 : "=r"(r[0]), "=r"(r[1]), "=r"(r[2]), "=r"(r[3]) : "r"(addr));
}
__device__ __forceinline__ void ldsm4t(u32* r, u32 addr) {
    asm volatile("ldmatrix.sync.aligned.m8n8.x4.trans.shared.b16 {%0,%1,%2,%3}, [%4];"
                 : "=r"(r[0]), "=r"(r[1]), "=r"(r[2]), "=r"(r[3]) : "r"(addr));
}
__device__ __forceinline__ void mma16816(float* c, const u32* a, u32 b0, u32 b1) {
    asm volatile(
        "mma.sync.aligned.m16n8k16.row.col.f32.f16.f16.f32 "
        "{%0,%1,%2,%3}, {%4,%5,%6,%7}, {%8,%9}, {%0,%1,%2,%3};"
        : "+f"(c[0]), "+f"(c[1]), "+f"(c[2]), "+f"(c[3])
        : "r"(a[0]), "r"(a[1]), "r"(a[2]), "r"(a[3]), "r"(b0), "r"(b1));
}
__device__ __forceinline__ u32 pack_h2(float e0, float e1) {
    u32 r;
    asm("cvt.rn.f16x2.f32 %0, %1, %2;" : "=r"(r) : "f"(e1), "f"(e0));  // e0 low, e1 high
    return r;
}

// ============================================================================
// Prep kernels
// ============================================================================
__global__ void prep_weights(const float* __restrict__ Wq0, const float* __restrict__ Wkv0,
                             const float* __restrict__ Wout0,
                             const float* __restrict__ Wq1, const float* __restrict__ Wkv1,
                             const float* __restrict__ Wout1,
                             __half* __restrict__ Wh)
{
    const int m = blockIdx.x;      // 0..7 : [q0,k0,v0,o0,q1,k1,v1,o1]
    const int slab = blockIdx.y;   // 0..7
    const float* W;
    int ld = 256, coff = 0;
    float scale = 1.0f;
    switch (m & 3) {
        case 0: W = (m < 4) ? Wq0 : Wq1; scale = 0.17677669529663687f; break;  // 32^-0.5
        case 1: W = (m < 4) ? Wkv0 : Wkv1; ld = 512; break;
        case 2: W = (m < 4) ? Wkv0 : Wkv1; ld = 512; coff = 256; break;
        default: W = (m < 4) ? Wout0 : Wout1; break;
    }
    __half* dh = Wh + (size_t)m * 65536;
    for (int e = threadIdx.x; e < 8192; e += 256) {
        int n = slab * 32 + (e >> 8);
        int k = e & 255;
        dh[n * 256 + k] = __float2half_rn(W[k * ld + coff + n] * scale);  // B[n][k]=W[k][n]
    }
}

__global__ void cvt_x_kernel(const float* __restrict__ x, __half* __restrict__ xh)
{
    size_t i = ((size_t)blockIdx.x * 256 + threadIdx.x) * 4;
    float4 v = *(const float4*)(x + i);
    u32 w0 = pack_h2(v.x, v.y);
    u32 w1 = pack_h2(v.z, v.w);
    *(uint2*)((u16*)xh + i) = make_uint2(w0, w1);
}

// ============================================================================
// GEMM core: 128m x 128n x 256k, pure fp16 single pass, 3-stage cp.async.
// smem stage: Ah | Bh, each 128 rows x 32 k, 80B row stride.
// ============================================================================
#define GS_ROWB   80
#define GS_PART   10240
#define GS_STAGE  20480
#define GS_SMEM   61440     // 3 stages

__device__ __forceinline__ void gemm_mainloop(
    u32 sb, const __half* __restrict__ Ah, const __half* __restrict__ Bh,
    int rowBase, int colBase, int t, float acc[4][4][4])
{
    const int l = t & 31;
    const int wm = (t >> 5) >> 2;
    const int wn = (t >> 5) & 3;
    const int lr = t >> 2, lc = t & 3;
    const u32 lmOff = (u32)((l & 15) * GS_ROWB + (l >> 4) * 16);

    auto prefetch = [&](int kc) {
        const u32 stb = sb + (u32)(kc % 3) * GS_STAGE;
        const int kcol = kc * 32;
#pragma unroll
        for (int i = 0; i < 2; i++) {
            const int r = lr + i * 64;
            const u32 doff = (u32)(r * GS_ROWB + lc * 16);
            const size_t gA = (size_t)(rowBase + r) * 256 + kcol + lc * 8;
            const size_t gB = (size_t)(colBase + r) * 256 + kcol + lc * 8;
            cpasync16(stb + doff,           Ah + gA);
            cpasync16(stb + GS_PART + doff, Bh + gB);
        }
        cp_commit();
    };

    prefetch(0);
    prefetch(1);

    for (int kc = 0; kc < 8; kc++) {
        if (kc < 7) cp_wait<1>(); else cp_wait<0>();
        __syncthreads();
        if (kc < 6) prefetch(kc + 2);

        const u32 stb = sb + (u32)(kc % 3) * GS_STAGE;
#pragma unroll
        for (int ks = 0; ks < 2; ks++) {
            u32 ah[4][4];
#pragma unroll
            for (int mf = 0; mf < 4; mf++) {
                const u32 a = stb + (u32)((wm * 64 + mf * 16) * GS_ROWB + ks * 32) + lmOff;
                ldsm4(ah[mf], a);
            }
            u32 bh[2][4];
#pragma unroll
            for (int g = 0; g < 2; g++) {
                const u32 b = stb + GS_PART
                            + (u32)((wn * 32 + g * 16) * GS_ROWB + ks * 32) + lmOff;
                ldsm4(bh[g], b);
            }
            // 16 independent accumulators -> no RAW chains
#pragma unroll
            for (int mf = 0; mf < 4; mf++)
#pragma unroll
                for (int nf = 0; nf < 4; nf++)
                    mma16816(acc[mf][nf], ah[mf], bh[nf >> 1][nf & 1], bh[nf >> 1][(nf & 1) + 2]);
        }
    }
}

// ---- fused QKV projection: grid (6, 1024): x -> Q|K|V fp16 ----
__global__ void __launch_bounds__(256)
gemm_qkv(const __half* __restrict__ Ah, const __half* __restrict__ Bbase,
         __half* __restrict__ Qh, __half* __restrict__ Kh, __half* __restrict__ Vh)
{
    extern __shared__ __align__(128) char smem[];
    const u32 sb = smem_u32(smem);
    const int t = threadIdx.x;
    const int bx = blockIdx.x;
    const int mat = bx >> 1;                 // 0=Q 1=K 2=V
    const int colBase = (bx & 1) << 7;
    const int rowBase = blockIdx.y << 7;

    const __half* Bm = Bbase + (size_t)mat * 65536;
    __half* Ch = (mat == 0) ? Qh : (mat == 1) ? Kh : Vh;

    float acc[4][4][4];
#pragma unroll
    for (int i = 0; i < 4; i++)
#pragma unroll
        for (int j = 0; j < 4; j++)
#pragma unroll
            for (int q = 0; q < 4; q++) acc[i][j][q] = 0.f;

    gemm_mainloop(sb, Ah, Bm, rowBase, colBase, t, acc);

    const int l = t & 31;
    const int wm = (t >> 5) >> 2, wn = (t >> 5) & 3;
#pragma unroll
    for (int mf = 0; mf < 4; mf++) {
        const int m0 = rowBase + wm * 64 + mf * 16 + (l >> 2);
#pragma unroll
        for (int nf = 0; nf < 4; nf++) {
            const int col = colBase + wn * 32 + nf * 8 + 2 * (l & 3);
            const size_t i0 = (size_t)m0 * 256 + col;
            const size_t i1 = i0 + 8 * 256;
            *(u32*)((u16*)Ch + i0) = pack_h2(acc[mf][nf][0], acc[mf][nf][1]);
            *(u32*)((u16*)Ch + i1) = pack_h2(acc[mf][nf][2], acc[mf][nf][3]);
        }
    }
}

// ---- out-projection: f32 out + bias (+accum) ----
template<bool ACCUM>
__global__ void __launch_bounds__(256)
gemm_out(const __half* __restrict__ Ah, const __half* __restrict__ Bm,
         float* __restrict__ C, const float* __restrict__ bias)
{
    extern __shared__ __align__(128) char smem[];
    const u32 sb = smem_u32(smem);
    const int t = threadIdx.x;
    const int rowBase = blockIdx.y << 7;
    const int colBase = blockIdx.x << 7;

    float acc[4][4][4];
#pragma unroll
    for (int i = 0; i < 4; i++)
#pragma unroll
        for (int j = 0; j < 4; j++)
#pragma unroll
            for (int q = 0; q < 4; q++) acc[i][j][q] = 0.f;

    gemm_mainloop(sb, Ah, Bm, rowBase, colBase, t, acc);

    const int l = t & 31;
    const int wm = (t >> 5) >> 2, wn = (t >> 5) & 3;
#pragma unroll
    for (int mf = 0; mf < 4; mf++) {
        const int m0 = rowBase + wm * 64 + mf * 16 + (l >> 2);
#pragma unroll
        for (int nf = 0; nf < 4; nf++) {
            const int col = colBase + wn * 32 + nf * 8 + 2 * (l & 3);
            float2 v0 = make_float2(acc[mf][nf][0], acc[mf][nf][1]);
            float2 v1 = make_float2(acc[mf][nf][2], acc[mf][nf][3]);
            float2 b = *(const float2*)(bias + col);
            v0.x += b.x; v0.y += b.y; v1.x += b.x; v1.y += b.y;
            float* p0 = C + (size_t)m0 * 256 + col;
            float* p1 = p0 + 8 * 256;
            if (ACCUM) {
                float2 c0 = *(float2*)p0, c1 = *(float2*)p1;
                v0.x += c0.x; v0.y += c0.y; v1.x += c1.x; v1.y += c1.y;
            }
            *(float2*)p0 = v0;
            *(float2*)p1 = v1;
        }
    }
}

// ============================================================================
// HMMA attention: one block per (sequence, head). seqlen=128, e=32.
// Warp w owns query rows w*16..+15 (quad-only softmax reductions).
// Pure fp16: S = Q K^T ; O = P V.  smem tiles: Q | K | V (128 x 32, 80B rows).
// ============================================================================
#define AT_ROWB 80
#define AT_TILE 10240
#define AT_SMEM (3 * AT_TILE)   // 30720

__global__ void __launch_bounds__(256, 2)
attn_mma(const __half* __restrict__ Qh, const __half* __restrict__ Kh,
         const __half* __restrict__ Vh, __half* __restrict__ Oh, int axis)
{
    extern __shared__ __align__(128) char smem[];
    const u32 sb = smem_u32(smem);
    const int t = threadIdx.x;
    const int l = t & 31;
    const int w = t >> 5;

    const int s = blockIdx.x;
    const int head = blockIdx.y;
    int tokBase, tokStride;
    if (axis == 0) { int b = s >> 7, ww = s & 127; tokBase = b * 16384 + ww; tokStride = 128; }
    else           { tokBase = s * 128; tokStride = 1; }
    const int chanOff = head * 32;

    // ---- load 3 tiles (cp.async, one shot) ----
    {
        const __half* srcs[3] = { Qh, Kh, Vh };
#pragma unroll
        for (int tile = 0; tile < 3; tile++) {
            const u16* src = (const u16*)srcs[tile];
#pragma unroll
            for (int i = 0; i < 2; i++) {
                const int c = t + i * 256;
                const int row = c >> 2, cg = c & 3;
                const size_t g = (size_t)(tokBase + row * tokStride) * 256 + chanOff + cg * 8;
                cpasync16(sb + tile * AT_TILE + row * AT_ROWB + cg * 16, src + g);
            }
        }
        cp_commit();
        cp_wait<0>();
        __syncthreads();
    }

    const u32 lmOff = (u32)((l & 15) * AT_ROWB + (l >> 4) * 16);

    // ---- S = Q K^T, warp strip rows w*16..+15, full 128 cols ----
    float sv[16][4];
#pragma unroll
    for (int nf = 0; nf < 16; nf++)
#pragma unroll
        for (int q = 0; q < 4; q++) sv[nf][q] = 0.f;

#pragma unroll
    for (int kc = 0; kc < 2; kc++) {
        u32 aq[4];
        const u32 qa = sb + (u32)(w * 16 * AT_ROWB + kc * 32) + lmOff;
        ldsm4(aq, qa);
#pragma unroll
        for (int gp = 0; gp < 4; gp++) {
            u32 kh4[2][4];
#pragma unroll
            for (int gi = 0; gi < 2; gi++) {
                const int g = gp * 2 + gi;
                const u32 ka = sb + AT_TILE + (u32)(g * 16 * AT_ROWB + kc * 32) + lmOff;
                ldsm4(kh4[gi], ka);
            }
#pragma unroll
            for (int gi = 0; gi < 2; gi++)
#pragma unroll
                for (int j = 0; j < 2; j++)
                    mma16816(sv[(gp * 2 + gi) * 2 + j], aq, kh4[gi][j], kh4[gi][j + 2]);
        }
    }

    // ---- softmax (rows fully in-warp: quad shuffles only) ----
    float mx0 = -1e30f, mx1 = -1e30f;
#pragma unroll
    for (int nf = 0; nf < 16; nf++) {
        mx0 = fmaxf(mx0, fmaxf(sv[nf][0], sv[nf][1]));
        mx1 = fmaxf(mx1, fmaxf(sv[nf][2], sv[nf][3]));
    }
    mx0 = fmaxf(mx0, __shfl_xor_sync(0xffffffffu, mx0, 1));
    mx0 = fmaxf(mx0, __shfl_xor_sync(0xffffffffu, mx0, 2));
    mx1 = fmaxf(mx1, __shfl_xor_sync(0xffffffffu, mx1, 1));
    mx1 = fmaxf(mx1, __shfl_xor_sync(0xffffffffu, mx1, 2));

    float sum0 = 0.f, sum1 = 0.f;
#pragma unroll
    for (int nf = 0; nf < 16; nf++) {
        sv[nf][0] = __expf(sv[nf][0] - mx0);
        sv[nf][1] = __expf(sv[nf][1] - mx0);
        sv[nf][2] = __expf(sv[nf][2] - mx1);
        sv[nf][3] = __expf(sv[nf][3] - mx1);
        sum0 += sv[nf][0] + sv[nf][1];
        sum1 += sv[nf][2] + sv[nf][3];
    }
    sum0 += __shfl_xor_sync(0xffffffffu, sum0, 1);
    sum0 += __shfl_xor_sync(0xffffffffu, sum0, 2);
    sum1 += __shfl_xor_sync(0xffffffffu, sum1, 1);
    sum1 += __shfl_xor_sync(0xffffffffu, sum1, 2);
    const float inv0 = 1.0f / sum0;
    const float inv1 = 1.0f / sum1;

    // ---- O = P V, P frags packed fp16 in-register ----
    float ao[4][4];
#pragma unroll
    for (int nf = 0; nf < 4; nf++)
#pragma unroll
        for (int q = 0; q < 4; q++) ao[nf][q] = 0.f;

#pragma unroll
    for (int jc = 0; jc < 8; jc++) {
        u32 ph[4];
        ph[0] = pack_h2(sv[2 * jc][0],     sv[2 * jc][1]);
        ph[1] = pack_h2(sv[2 * jc][2],     sv[2 * jc][3]);
        ph[2] = pack_h2(sv[2 * jc + 1][0], sv[2 * jc + 1][1]);
        ph[3] = pack_h2(sv[2 * jc + 1][2], sv[2 * jc + 1][3]);
        u32 vh4[2][4];
#pragma unroll
        for (int eg = 0; eg < 2; eg++) {
            const u32 va = sb + 2 * AT_TILE + (u32)(jc * 16 * AT_ROWB + eg * 32) + lmOff;
            ldsm4t(vh4[eg], va);
        }
#pragma unroll
        for (int eg = 0; eg < 2; eg++)
#pragma unroll
            for (int j = 0; j < 2; j++)
                mma16816(ao[eg * 2 + j], ph, vh4[eg][j * 2], vh4[eg][j * 2 + 1]);
    }

    // ---- normalize + write fp16 ----
    const int row0 = w * 16 + (l >> 2);
    const int row1 = row0 + 8;
    const size_t tok0 = (size_t)(tokBase + row0 * tokStride) * 256;
    const size_t tok1 = (size_t)(tokBase + row1 * tokStride) * 256;
#pragma unroll
    for (int nf = 0; nf < 4; nf++) {
        const int col = chanOff + nf * 8 + 2 * (l & 3);
        *(u32*)((u16*)Oh + tok0 + col) = pack_h2(ao[nf][0] * inv0, ao[nf][1] * inv0);
        *(u32*)((u16*)Oh + tok1 + col) = pack_h2(ao[nf][2] * inv1, ao[nf][3] * inv1);
    }
}

// ============================================================================
// Host launcher
// ============================================================================
extern "C" void kernel_launch(void* const* d_in, const int* in_sizes, int n_in,
                              void* d_out, int out_size)
{
    (void)in_sizes; (void)n_in; (void)out_size;
    const float* x     = (const float*)d_in[0];
    const float* Wq0   = (const float*)d_in[1];
    const float* Wkv0  = (const float*)d_in[2];
    const float* Wout0 = (const float*)d_in[3];
    const float* bout0 = (const float*)d_in[4];
    const float* Wq1   = (const float*)d_in[5];
    const float* Wkv1  = (const float*)d_in[6];
    const float* Wout1 = (const float*)d_in[7];
    const float* bout1 = (const float*)d_in[8];
    float* out = (float*)d_out;

    __half *xh, *Qhb, *Khb, *Vhb, *Ohb, *Wh;
    cudaGetSymbolAddress((void**)&xh,  g_xh);
    cudaGetSymbolAddress((void**)&Qhb, g_Qh);
    cudaGetSymbolAddress((void**)&Khb, g_Kh);
    cudaGetSymbolAddress((void**)&Vhb, g_Vh);
    cudaGetSymbolAddress((void**)&Ohb, g_Oh);
    cudaGetSymbolAddress((void**)&Wh,  g_Wh);

    cudaFuncSetAttribute(gemm_qkv,
                         cudaFuncAttributeMaxDynamicSharedMemorySize, GS_SMEM);
    cudaFuncSetAttribute(gemm_out<false>,
                         cudaFuncAttributeMaxDynamicSharedMemorySize, GS_SMEM);
    cudaFuncSetAttribute(gemm_out<true>,
                         cudaFuncAttributeMaxDynamicSharedMemorySize, GS_SMEM);
    cudaFuncSetAttribute(attn_mma,
                         cudaFuncAttributeMaxDynamicSharedMemorySize, AT_SMEM);

    const dim3 gq(6, 1024);    // fused QKV: (mat*2 + ntile, m tiles)
    const dim3 gg(2, 1024);    // out-proj
    const dim3 ga(1024, 8);    // (sequences, heads)

    prep_weights<<<dim3(8, 8), 256>>>(Wq0, Wkv0, Wout0, Wq1, Wkv1, Wout1, Wh);
    cvt_x_kernel<<<32768, 256>>>(x, xh);

    // ---- axis 0 ----
    gemm_qkv<<<gq, 256, GS_SMEM>>>(xh, Wh, Qhb, Khb, Vhb);
    attn_mma<<<ga, 256, AT_SMEM>>>(Qhb, Khb, Vhb, Ohb, 0);
    gemm_out<false><<<gg, 256, GS_SMEM>>>(Ohb, Wh + 3u * 65536, out, bout0);

    // ---- axis 1 ----
    gemm_qkv<<<gq, 256, GS_SMEM>>>(xh, Wh + 4u * 65536, Qhb, Khb, Vhb);
    attn_mma<<<ga, 256, AT_SMEM>>>(Qhb, Khb, Vhb, Ohb, 1);
    gemm_out<true><<<gg, 256, GS_SMEM>>>(Ohb, Wh + 7u * 65536, out, bout1);
}